// round 10
// baseline (speedup 1.0000x reference)
#include <cuda_runtime.h>
#include <math.h>

#define N_NODES 50000
#define E_EDGES 800000
#define E_TOT   (E_EDGES + N_NODES)
#define IN_DIM  512
#define F1      256
#define NH1     4
#define F2      40
#define NEG_SLOPE 0.2f
#define NINF (-__int_as_float(0x7f800000))
#define SCAN_BLOCKS 196   // 196*256 = 50176 >= N_NODES

// ---------------- scratch (static device allocations only) ----------------
__device__ int   g_is64;
__device__ int   g_src[E_EDGES];
__device__ int   g_dst[E_EDGES];
__device__ int   g_deg[N_NODES];
__device__ int   g_bsum[SCAN_BLOCKS];
__device__ int   g_rowstart[N_NODES + 1];
__device__ int   g_cursor[N_NODES];
__device__ int   g_csr[E_TOT];
__device__ __align__(16) float g_h1[(size_t)N_NODES * F1];
__device__ __align__(16) float g_as1[N_NODES * NH1];
__device__ __align__(16) float g_ad1[N_NODES * NH1];
__device__ __align__(16) float g_hmid[(size_t)N_NODES * F1];
__device__ __align__(16) float g_h2[(size_t)N_NODES * F2];
__device__ float g_as2[N_NODES];
__device__ float g_ad2[N_NODES];

// ---------------- helpers ----------------
__device__ __forceinline__ float lrelu(float x) { return x > 0.f ? x : NEG_SLOPE * x; }

__device__ __forceinline__ unsigned long long pk2(float lo, float hi) {
    unsigned long long r;
    asm("mov.b64 %0, {%1, %2};" : "=l"(r) : "f"(lo), "f"(hi));
    return r;
}
__device__ __forceinline__ void fma2(unsigned long long& d, unsigned long long a,
                                     unsigned long long b) {
    asm("fma.rn.f32x2 %0, %1, %2, %0;" : "+l"(d) : "l"(a), "l"(b));
}
__device__ __forceinline__ float2 upk2(unsigned long long v) {
    float2 r;
    asm("mov.b64 {%0, %1}, %2;" : "=f"(r.x), "=f"(r.y) : "l"(v));
    return r;
}

// ---------------- init: self-loop degree, zero attn accumulators, dtype detect ----
__global__ void k_init(const int* e32) {
    int i = blockIdx.x * blockDim.x + threadIdx.x;
    if (i < N_NODES) {
        g_deg[i] = 1;  // self loop
        *(float4*)&g_as1[i * 4] = make_float4(0.f, 0.f, 0.f, 0.f);
        *(float4*)&g_ad1[i * 4] = make_float4(0.f, 0.f, 0.f, 0.f);
    }
    if (i == 0) {
        int allzero = 1;
        for (int j = 1; j < 256; j += 2) if (e32[j] != 0) allzero = 0;
        g_is64 = allzero;
    }
}

__global__ void k_convert_count(const void* eptr) {
    int i = blockIdx.x * blockDim.x + threadIdx.x;
    if (i >= E_EDGES) return;
    int s, d;
    if (g_is64) {
        const long long* e = (const long long*)eptr;
        s = (int)e[i];
        d = (int)e[E_EDGES + i];
    } else {
        const int* e = (const int*)eptr;
        s = e[i];
        d = e[E_EDGES + i];
    }
    g_src[i] = s;
    g_dst[i] = d;
    atomicAdd(&g_deg[d], 1);
}

// ---------------- CSR scan (2 kernels) ----------------
__global__ void k_bsum() {
    __shared__ int sh[256];
    const int b = blockIdx.x, t = threadIdx.x;
    const int i = b * 256 + t;
    sh[t] = (i < N_NODES) ? g_deg[i] : 0;
    __syncthreads();
#pragma unroll
    for (int off = 128; off; off >>= 1) {
        if (t < off) sh[t] += sh[t + off];
        __syncthreads();
    }
    if (t == 0) g_bsum[b] = sh[0];
}

// per-block prefix of bsum computed locally; then local scan writes rowstart
__global__ void k_rowstart2() {
    __shared__ int sred[256];
    __shared__ int sh[256];
    const int b = blockIdx.x, t = threadIdx.x;
    sred[t] = (t < b) ? g_bsum[t] : 0;   // b <= 195 < 256
    __syncthreads();
#pragma unroll
    for (int off = 128; off; off >>= 1) {
        if (t < off) sred[t] += sred[t + off];
        __syncthreads();
    }
    const int boff = sred[0];

    const int i = b * 256 + t;
    const int v = (i < N_NODES) ? g_deg[i] : 0;
    sh[t] = v;
    __syncthreads();
#pragma unroll
    for (int off = 1; off < 256; off <<= 1) {
        int u = (t >= off) ? sh[t - off] : 0;
        __syncthreads();
        sh[t] += u;
        __syncthreads();
    }
    const int excl = boff + sh[t] - v;
    if (i < N_NODES) {
        g_rowstart[i] = excl;
        g_cursor[i]   = excl;
        if (i == N_NODES - 1) g_rowstart[N_NODES] = excl + v;
    }
}

__global__ void k_scatter() {
    int i = blockIdx.x * blockDim.x + threadIdx.x;
    if (i >= E_TOT) return;
    int s, d;
    if (i < E_EDGES) { s = g_src[i]; d = g_dst[i]; }
    else             { s = d = i - E_EDGES; }
    int pos = atomicAdd(&g_cursor[d], 1);
    g_csr[pos] = s;
}

// ---------------- GEMM1 + fused attention dots ----------------
// 64x128x16 tiles, 256 threads, 4x8 per thread, 3 CTAs/SM target (latency hiding).
// Inner loop: 3 LDS.128 + 16 FFMA2 per kk.
#define BM 64
#define BN 128
#define BK 16
#define APAD 68    // row stride 272B = 17*16B: float4-aligned, bank skew 4
__global__ __launch_bounds__(256, 3) void k_gemm1(const float* __restrict__ x,
                                                  const float* __restrict__ W,
                                                  const float* __restrict__ atts,
                                                  const float* __restrict__ attd) {
    __shared__ __align__(16) float As[2][BK][APAD];
    __shared__ __align__(16) float Bs[2][BK][BN];
    const int bm = blockIdx.y * BM, bn = blockIdx.x * BN;
    const int t = threadIdx.x;
    const int w = t >> 5, l = t & 31;
    const int tx = ((w & 1) << 3) | (l & 7);     // 0..15, 8 distinct per warp
    const int ty = ((w >> 1) << 2) | (l >> 3);   // 0..15, 4 distinct per warp
    const int arow = t >> 2;            // 0..63
    const int akv  = (t & 3) * 4;       // k offset
    const int brow0 = t >> 5;           // 0..7 (+8 second)
    const int bcv   = (t & 31) * 4;

    unsigned long long acc[4][4];
#pragma unroll
    for (int i = 0; i < 4; i++)
#pragma unroll
        for (int j = 0; j < 4; j++) acc[i][j] = 0ULL;

    float4 pa, pb[2];
    {
        int gr = bm + arow;
        pa = make_float4(0.f, 0.f, 0.f, 0.f);
        if (gr < N_NODES) pa = *(const float4*)&x[(size_t)gr * IN_DIM + akv];
#pragma unroll
        for (int r = 0; r < 2; r++)
            pb[r] = *(const float4*)&W[(size_t)(brow0 + 8 * r) * F1 + bn + bcv];
    }
    As[0][akv + 0][arow] = pa.x;
    As[0][akv + 1][arow] = pa.y;
    As[0][akv + 2][arow] = pa.z;
    As[0][akv + 3][arow] = pa.w;
#pragma unroll
    for (int r = 0; r < 2; r++)
        *(float4*)&Bs[0][brow0 + 8 * r][bcv] = pb[r];
    __syncthreads();

    int buf = 0;
    for (int k0 = 0; k0 < IN_DIM; k0 += BK) {
        const bool has_next = (k0 + BK) < IN_DIM;
        if (has_next) {
            int gr = bm + arow;
            pa = make_float4(0.f, 0.f, 0.f, 0.f);
            if (gr < N_NODES)
                pa = *(const float4*)&x[(size_t)gr * IN_DIM + k0 + BK + akv];
#pragma unroll
            for (int r = 0; r < 2; r++)
                pb[r] = *(const float4*)&W[(size_t)(k0 + BK + brow0 + 8 * r) * F1 + bn + bcv];
        }
#pragma unroll
        for (int kk = 0; kk < BK; kk++) {
            ulonglong2 bv0 = *(const ulonglong2*)&Bs[buf][kk][tx * 8];
            ulonglong2 bv1 = *(const ulonglong2*)&Bs[buf][kk][tx * 8 + 4];
            float4 a4 = *(const float4*)&As[buf][kk][ty * 4];
            float a[4] = {a4.x, a4.y, a4.z, a4.w};
#pragma unroll
            for (int i = 0; i < 4; i++) {
                unsigned long long aa = pk2(a[i], a[i]);
                fma2(acc[i][0], aa, bv0.x);
                fma2(acc[i][1], aa, bv0.y);
                fma2(acc[i][2], aa, bv1.x);
                fma2(acc[i][3], aa, bv1.y);
            }
        }
        if (has_next) {
            As[buf ^ 1][akv + 0][arow] = pa.x;
            As[buf ^ 1][akv + 1][arow] = pa.y;
            As[buf ^ 1][akv + 2][arow] = pa.z;
            As[buf ^ 1][akv + 3][arow] = pa.w;
#pragma unroll
            for (int r = 0; r < 2; r++)
                *(float4*)&Bs[buf ^ 1][brow0 + 8 * r][bcv] = pb[r];
            __syncthreads();
            buf ^= 1;
        }
    }

    // epilogue: store h1 + fused attention partial dots.
    // 8 consecutive lanes share ty and cover one 64-col head.
    const int col0 = bn + tx * 8;
    const int head = col0 >> 6;
    float avS[8], avD[8];
#pragma unroll
    for (int j = 0; j < 8; j++) { avS[j] = atts[col0 + j]; avD[j] = attd[col0 + j]; }

#pragma unroll
    for (int i = 0; i < 4; i++) {
        int gr = bm + ty * 4 + i;
        float2 c0 = upk2(acc[i][0]), c1 = upk2(acc[i][1]);
        float2 c2 = upk2(acc[i][2]), c3 = upk2(acc[i][3]);
        float cv[8] = {c0.x, c0.y, c1.x, c1.y, c2.x, c2.y, c3.x, c3.y};
        if (gr < N_NODES) {
            *(float4*)&g_h1[(size_t)gr * F1 + col0]     = make_float4(cv[0], cv[1], cv[2], cv[3]);
            *(float4*)&g_h1[(size_t)gr * F1 + col0 + 4] = make_float4(cv[4], cv[5], cv[6], cv[7]);
        }
        float ps = 0.f, pd = 0.f;
#pragma unroll
        for (int j = 0; j < 8; j++) {
            ps = fmaf(cv[j], avS[j], ps);
            pd = fmaf(cv[j], avD[j], pd);
        }
#pragma unroll
        for (int off = 4; off; off >>= 1) {
            ps += __shfl_down_sync(0xffffffffu, ps, off, 8);
            pd += __shfl_down_sync(0xffffffffu, pd, off, 8);
        }
        if ((l & 7) == 0 && gr < N_NODES) {
            atomicAdd(&g_as1[gr * 4 + head], ps);
            atomicAdd(&g_ad1[gr * 4 + head], pd);
        }
    }
}

// ---------------- layer-1 aggregation: WARP per node ----------------
__global__ __launch_bounds__(256) void k_agg1w(const float* __restrict__ b1) {
    const int node = blockIdx.x * 8 + (threadIdx.x >> 5);  // 6250*8 = 50000 exact
    const int lane = threadIdx.x & 31;
    const int start = g_rowstart[node];
    const int cnt = g_rowstart[node + 1] - start;

    float4 adv = *(const float4*)&g_ad1[node * 4];

    float m0 = NINF, m1 = NINF, m2 = NINF, m3 = NINF;
    for (int e = lane; e < cnt; e += 32) {
        int s = g_csr[start + e];
        float4 av = *(const float4*)&g_as1[s * 4];
        m0 = fmaxf(m0, lrelu(av.x + adv.x));
        m1 = fmaxf(m1, lrelu(av.y + adv.y));
        m2 = fmaxf(m2, lrelu(av.z + adv.z));
        m3 = fmaxf(m3, lrelu(av.w + adv.w));
    }
#pragma unroll
    for (int off = 16; off; off >>= 1) {
        m0 = fmaxf(m0, __shfl_xor_sync(0xffffffffu, m0, off));
        m1 = fmaxf(m1, __shfl_xor_sync(0xffffffffu, m1, off));
        m2 = fmaxf(m2, __shfl_xor_sync(0xffffffffu, m2, off));
        m3 = fmaxf(m3, __shfl_xor_sync(0xffffffffu, m3, off));
    }

    float s0 = 0.f, s1 = 0.f, s2 = 0.f, s3 = 0.f;
    for (int e = lane; e < cnt; e += 32) {
        int s = g_csr[start + e];
        float4 av = *(const float4*)&g_as1[s * 4];
        s0 += expf(lrelu(av.x + adv.x) - m0);
        s1 += expf(lrelu(av.y + adv.y) - m1);
        s2 += expf(lrelu(av.z + adv.z) - m2);
        s3 += expf(lrelu(av.w + adv.w) - m3);
    }
#pragma unroll
    for (int off = 16; off; off >>= 1) {
        s0 += __shfl_xor_sync(0xffffffffu, s0, off);
        s1 += __shfl_xor_sync(0xffffffffu, s1, off);
        s2 += __shfl_xor_sync(0xffffffffu, s2, off);
        s3 += __shfl_xor_sync(0xffffffffu, s3, off);
    }

    const int hh = lane >> 3;
    float advh = (hh == 0) ? adv.x : (hh == 1) ? adv.y : (hh == 2) ? adv.z : adv.w;
    float mh   = (hh == 0) ? m0    : (hh == 1) ? m1    : (hh == 2) ? m2    : m3;
    float sumh = (hh == 0) ? s0    : (hh == 1) ? s1    : (hh == 2) ? s2    : s3;
    const float invh = 1.f / (sumh + 1e-16f);

    float4 a0 = make_float4(0.f, 0.f, 0.f, 0.f);
    float4 a1 = make_float4(0.f, 0.f, 0.f, 0.f);
    const int coff = lane * 8;
    for (int e = 0; e < cnt; e++) {
        int s = g_csr[start + e];
        float av = __ldg(&g_as1[s * 4 + hh]);
        float al = expf(lrelu(av + advh) - mh) * invh;
        const float* row = &g_h1[(size_t)s * F1 + coff];
        float4 v0 = *(const float4*)row;
        float4 v1 = *(const float4*)(row + 4);
        a0.x = fmaf(al, v0.x, a0.x); a0.y = fmaf(al, v0.y, a0.y);
        a0.z = fmaf(al, v0.z, a0.z); a0.w = fmaf(al, v0.w, a0.w);
        a1.x = fmaf(al, v1.x, a1.x); a1.y = fmaf(al, v1.y, a1.y);
        a1.z = fmaf(al, v1.z, a1.z); a1.w = fmaf(al, v1.w, a1.w);
    }

    float4 bb0 = *(const float4*)&b1[coff];
    float4 bb1 = *(const float4*)&b1[coff + 4];
    float r0 = a0.x + bb0.x, r1 = a0.y + bb0.y, r2 = a0.z + bb0.z, r3 = a0.w + bb0.w;
    float r4 = a1.x + bb1.x, r5 = a1.y + bb1.y, r6 = a1.z + bb1.z, r7 = a1.w + bb1.w;
    r0 = r0 > 0.f ? r0 : expm1f(r0); r1 = r1 > 0.f ? r1 : expm1f(r1);
    r2 = r2 > 0.f ? r2 : expm1f(r2); r3 = r3 > 0.f ? r3 : expm1f(r3);
    r4 = r4 > 0.f ? r4 : expm1f(r4); r5 = r5 > 0.f ? r5 : expm1f(r5);
    r6 = r6 > 0.f ? r6 : expm1f(r6); r7 = r7 > 0.f ? r7 : expm1f(r7);
    float* orow = &g_hmid[(size_t)node * F1 + coff];
    *(float4*)orow       = make_float4(r0, r1, r2, r3);
    *(float4*)(orow + 4) = make_float4(r4, r5, r6, r7);
}

// ---------------- GEMM2 + fused attention dots (transposed A, conflict-free) ----
#define BM2 128
#define BK2 32
#define A2PAD 132
__global__ __launch_bounds__(256) void k_gemm2(const float* __restrict__ W2,
                                               const float* __restrict__ atts,
                                               const float* __restrict__ attd) {
    __shared__ __align__(16) float As2t[BK2][A2PAD];
    __shared__ __align__(16) float Ws[BK2][F2];
    const int bm = blockIdx.x * BM2;
    const int t = threadIdx.x;
    const int tx = t & 7;
    const int ty = t >> 3;
    float acc[4][5];
#pragma unroll
    for (int i = 0; i < 4; i++)
#pragma unroll
        for (int j = 0; j < 5; j++) acc[i][j] = 0.f;

    for (int k0 = 0; k0 < F1; k0 += BK2) {
#pragma unroll
        for (int r = 0; r < 4; r++) {
            int f = t + r * 256;
            int row = f >> 3;
            int cv = (f & 7) * 4;
            float4 v = make_float4(0.f, 0.f, 0.f, 0.f);
            int gr = bm + row;
            if (gr < N_NODES) v = *(const float4*)&g_hmid[(size_t)gr * F1 + k0 + cv];
            As2t[cv + 0][row] = v.x;
            As2t[cv + 1][row] = v.y;
            As2t[cv + 2][row] = v.z;
            As2t[cv + 3][row] = v.w;
        }
        for (int idx = t; idx < BK2 * F2; idx += 256) {
            int r = idx / F2, c = idx % F2;
            Ws[r][c] = W2[(size_t)(k0 + r) * F2 + c];
        }
        __syncthreads();
#pragma unroll
        for (int kk = 0; kk < BK2; kk++) {
            float4 a4 = *(const float4*)&As2t[kk][ty * 4];
            float a[4] = {a4.x, a4.y, a4.z, a4.w};
            float b[5];
#pragma unroll
            for (int j = 0; j < 5; j++) b[j] = Ws[kk][tx * 5 + j];
#pragma unroll
            for (int i = 0; i < 4; i++)
#pragma unroll
                for (int j = 0; j < 5; j++) acc[i][j] = fmaf(a[i], b[j], acc[i][j]);
        }
        __syncthreads();
    }

    float avS[5], avD[5];
#pragma unroll
    for (int j = 0; j < 5; j++) { avS[j] = atts[tx * 5 + j]; avD[j] = attd[tx * 5 + j]; }
#pragma unroll
    for (int i = 0; i < 4; i++) {
        int gr = bm + ty * 4 + i;
        if (gr < N_NODES)
#pragma unroll
            for (int j = 0; j < 5; j++)
                g_h2[(size_t)gr * F2 + tx * 5 + j] = acc[i][j];
        float ps = 0.f, pd = 0.f;
#pragma unroll
        for (int j = 0; j < 5; j++) {
            ps = fmaf(acc[i][j], avS[j], ps);
            pd = fmaf(acc[i][j], avD[j], pd);
        }
#pragma unroll
        for (int off = 4; off; off >>= 1) {
            ps += __shfl_down_sync(0xffffffffu, ps, off, 8);
            pd += __shfl_down_sync(0xffffffffu, pd, off, 8);
        }
        if (tx == 0 && gr < N_NODES) { g_as2[gr] = ps; g_ad2[gr] = pd; }
    }
}

// ---------------- layer-2 aggregation + log_softmax: WARP per node ----------------
__global__ __launch_bounds__(256) void k_agg2w(const float* __restrict__ b2,
                                               float* __restrict__ out) {
    const int node = blockIdx.x * 8 + (threadIdx.x >> 5);
    const int lane = threadIdx.x & 31;
    const int start = g_rowstart[node];
    const int cnt = g_rowstart[node + 1] - start;
    const float adv = g_ad2[node];

    float m = NINF;
    for (int e = lane; e < cnt; e += 32)
        m = fmaxf(m, lrelu(g_as2[g_csr[start + e]] + adv));
#pragma unroll
    for (int off = 16; off; off >>= 1)
        m = fmaxf(m, __shfl_xor_sync(0xffffffffu, m, off));

    float se = 0.f;
    for (int e = lane; e < cnt; e += 32)
        se += expf(lrelu(g_as2[g_csr[start + e]] + adv) - m);
#pragma unroll
    for (int off = 16; off; off >>= 1)
        se += __shfl_xor_sync(0xffffffffu, se, off);
    const float inv = 1.f / (se + 1e-16f);

    float a0 = 0.f, a1 = 0.f;
    for (int e = 0; e < cnt; e++) {
        int s = g_csr[start + e];
        float al = expf(lrelu(__ldg(&g_as2[s]) + adv) - m) * inv;
        const float* row = &g_h2[(size_t)s * F2];
        a0 = fmaf(al, row[lane], a0);
        if (lane < 8) a1 = fmaf(al, row[32 + lane], a1);
    }
    float v0 = a0 + b2[lane];
    float v1 = (lane < 8) ? (a1 + b2[32 + lane]) : NINF;

    float mm = fmaxf(v0, v1);
#pragma unroll
    for (int off = 16; off; off >>= 1)
        mm = fmaxf(mm, __shfl_xor_sync(0xffffffffu, mm, off));
    float s2 = expf(v0 - mm) + ((lane < 8) ? expf(v1 - mm) : 0.f);
#pragma unroll
    for (int off = 16; off; off >>= 1)
        s2 += __shfl_xor_sync(0xffffffffu, s2, off);
    const float lg = logf(s2);

    float* orow = &out[(size_t)node * F2];
    orow[lane] = v0 - mm - lg;
    if (lane < 8) orow[32 + lane] = v1 - mm - lg;
}

// ---------------- launch ----------------
extern "C" void kernel_launch(void* const* d_in, const int* in_sizes, int n_in,
                              void* d_out, int out_size) {
    const float* x   = (const float*)d_in[0];
    const void*  ei  = d_in[1];
    const float* W1  = (const float*)d_in[2];
    const float* as1 = (const float*)d_in[3];
    const float* ad1 = (const float*)d_in[4];
    const float* b1  = (const float*)d_in[5];
    const float* W2  = (const float*)d_in[6];
    const float* as2 = (const float*)d_in[7];
    const float* ad2 = (const float*)d_in[8];
    const float* b2  = (const float*)d_in[9];
    float* out = (float*)d_out;

    k_init<<<SCAN_BLOCKS, 256>>>((const int*)ei);            // #1
    k_convert_count<<<(E_EDGES + 255) / 256, 256>>>(ei);     // #2
    k_bsum<<<SCAN_BLOCKS, 256>>>();                          // #3
    dim3 g1(F1 / BN, (N_NODES + BM - 1) / BM);
    k_gemm1<<<g1, 256>>>(x, W1, as1, ad1);                   // #4  <- profiled
    k_rowstart2<<<SCAN_BLOCKS, 256>>>();                     // #5
    k_scatter<<<(E_TOT + 255) / 256, 256>>>();               // #6
    k_agg1w<<<N_NODES / 8, 256>>>(b1);                       // #7
    k_gemm2<<<(N_NODES + BM2 - 1) / BM2, 256>>>(W2, as2, ad2);  // #8
    k_agg2w<<<N_NODES / 8, 256>>>(b2, out);                  // #9
}

// round 11
// speedup vs baseline: 1.2289x; 1.2289x over previous
#include <cuda_runtime.h>
#include <math.h>

#define N_NODES 50000
#define E_EDGES 800000
#define E_TOT   (E_EDGES + N_NODES)
#define IN_DIM  512
#define F1      256
#define NH1     4
#define F2      40
#define NEG_SLOPE 0.2f
#define NINF (-__int_as_float(0x7f800000))
#define SCAN_BLOCKS 196   // 196*256 = 50176 >= N_NODES

// ---------------- scratch (static device allocations only) ----------------
__device__ int   g_is64;
__device__ int   g_src[E_EDGES];
__device__ int   g_dst[E_EDGES];
__device__ int   g_deg[N_NODES];
__device__ int   g_bsum[SCAN_BLOCKS];
__device__ int   g_rowstart[N_NODES + 1];
__device__ int   g_cursor[N_NODES];
__device__ int   g_csr[E_TOT];
__device__ __align__(16) float g_h1[(size_t)N_NODES * F1];
__device__ __align__(16) float g_as1[N_NODES * NH1];
__device__ __align__(16) float g_ad1[N_NODES * NH1];
__device__ __align__(16) float g_hmid[(size_t)N_NODES * F1];
__device__ __align__(16) float g_h2[(size_t)N_NODES * F2];
__device__ float g_as2[N_NODES];
__device__ float g_ad2[N_NODES];

// ---------------- helpers ----------------
__device__ __forceinline__ float lrelu(float x) { return x > 0.f ? x : NEG_SLOPE * x; }

__device__ __forceinline__ unsigned long long pk2(float lo, float hi) {
    unsigned long long r;
    asm("mov.b64 %0, {%1, %2};" : "=l"(r) : "f"(lo), "f"(hi));
    return r;
}
__device__ __forceinline__ void fma2(unsigned long long& d, unsigned long long a,
                                     unsigned long long b) {
    asm("fma.rn.f32x2 %0, %1, %2, %0;" : "+l"(d) : "l"(a), "l"(b));
}
__device__ __forceinline__ float2 upk2(unsigned long long v) {
    float2 r;
    asm("mov.b64 {%0, %1}, %2;" : "=f"(r.x), "=f"(r.y) : "l"(v));
    return r;
}

// ---------------- init: self-loop degree, zero attn accumulators, dtype detect ----
__global__ void k_init(const int* e32) {
    int i = blockIdx.x * blockDim.x + threadIdx.x;
    if (i < N_NODES) {
        g_deg[i] = 1;  // self loop
        *(float4*)&g_as1[i * 4] = make_float4(0.f, 0.f, 0.f, 0.f);
        *(float4*)&g_ad1[i * 4] = make_float4(0.f, 0.f, 0.f, 0.f);
    }
    if (i == 0) {
        int allzero = 1;
        for (int j = 1; j < 256; j += 2) if (e32[j] != 0) allzero = 0;
        g_is64 = allzero;
    }
}

__global__ void k_convert_count(const void* eptr) {
    int i = blockIdx.x * blockDim.x + threadIdx.x;
    if (i >= E_EDGES) return;
    int s, d;
    if (g_is64) {
        const long long* e = (const long long*)eptr;
        s = (int)e[i];
        d = (int)e[E_EDGES + i];
    } else {
        const int* e = (const int*)eptr;
        s = e[i];
        d = e[E_EDGES + i];
    }
    g_src[i] = s;
    g_dst[i] = d;
    atomicAdd(&g_deg[d], 1);
}

// ---------------- CSR scan (2 kernels) ----------------
__global__ void k_bsum() {
    __shared__ int sh[256];
    const int b = blockIdx.x, t = threadIdx.x;
    const int i = b * 256 + t;
    sh[t] = (i < N_NODES) ? g_deg[i] : 0;
    __syncthreads();
#pragma unroll
    for (int off = 128; off; off >>= 1) {
        if (t < off) sh[t] += sh[t + off];
        __syncthreads();
    }
    if (t == 0) g_bsum[b] = sh[0];
}

// per-block prefix of bsum computed locally; then local scan writes rowstart
__global__ void k_rowstart2() {
    __shared__ int sred[256];
    __shared__ int sh[256];
    const int b = blockIdx.x, t = threadIdx.x;
    sred[t] = (t < b) ? g_bsum[t] : 0;   // b <= 195 < 256
    __syncthreads();
#pragma unroll
    for (int off = 128; off; off >>= 1) {
        if (t < off) sred[t] += sred[t + off];
        __syncthreads();
    }
    const int boff = sred[0];

    const int i = b * 256 + t;
    const int v = (i < N_NODES) ? g_deg[i] : 0;
    sh[t] = v;
    __syncthreads();
#pragma unroll
    for (int off = 1; off < 256; off <<= 1) {
        int u = (t >= off) ? sh[t - off] : 0;
        __syncthreads();
        sh[t] += u;
        __syncthreads();
    }
    const int excl = boff + sh[t] - v;
    if (i < N_NODES) {
        g_rowstart[i] = excl;
        g_cursor[i]   = excl;
        if (i == N_NODES - 1) g_rowstart[N_NODES] = excl + v;
    }
}

__global__ void k_scatter() {
    int i = blockIdx.x * blockDim.x + threadIdx.x;
    if (i >= E_TOT) return;
    int s, d;
    if (i < E_EDGES) { s = g_src[i]; d = g_dst[i]; }
    else             { s = d = i - E_EDGES; }
    int pos = atomicAdd(&g_cursor[d], 1);
    g_csr[pos] = s;
}

// ---------------- GEMM1 + fused attention dots ----------------
// 128x128x32 tile, 8x8/thread (best measured shape), SINGLE smem buffer with
// register prefetch across the sync: same sync count as BK=16 double-buffer,
// but 2x longer compute bursts (32 kk) to hide LDS latency at occupancy 2.
#define BM 128
#define BN 128
#define BK 32
#define APAD 132
__global__ __launch_bounds__(256, 2) void k_gemm1(const float* __restrict__ x,
                                                  const float* __restrict__ W,
                                                  const float* __restrict__ atts,
                                                  const float* __restrict__ attd) {
    __shared__ __align__(16) float As[BK][APAD];   // transposed A tile (33KB total)
    __shared__ __align__(16) float Bs[BK][BN];
    const int bm = blockIdx.y * BM, bn = blockIdx.x * BN;
    const int t = threadIdx.x;
    const int w = t >> 5, l = t & 31;
    const int tx = ((w & 1) << 3) | (l & 7);     // 0..15, 8 distinct per warp
    const int ty = ((w >> 1) << 2) | (l >> 3);   // 0..15, 4 distinct per warp
    // A staging: 1024 float4 per tile, 4 per thread
    const int arow = t >> 3;            // 0..31 base rows (+32 per r)
    const int akv  = (t & 7) * 4;       // k offset 0..28
    // B staging: 1024 float4 per tile, 4 per thread
    const int brow = t >> 5;            // 0..7 (+8 per r)
    const int bcv  = (t & 31) * 4;

    unsigned long long acc[8][4];
#pragma unroll
    for (int i = 0; i < 8; i++)
#pragma unroll
        for (int j = 0; j < 4; j++) acc[i][j] = 0ULL;

    float4 pa[4], pb[4];
    // prologue: load tile k0=0
#pragma unroll
    for (int r = 0; r < 4; r++) {
        int row = arow + 32 * r;
        int gr = bm + row;
        pa[r] = make_float4(0.f, 0.f, 0.f, 0.f);
        if (gr < N_NODES) pa[r] = *(const float4*)&x[(size_t)gr * IN_DIM + akv];
        pb[r] = *(const float4*)&W[(size_t)(brow + 8 * r) * F1 + bn + bcv];
    }
#pragma unroll
    for (int r = 0; r < 4; r++) {
        int row = arow + 32 * r;
        As[akv + 0][row] = pa[r].x;
        As[akv + 1][row] = pa[r].y;
        As[akv + 2][row] = pa[r].z;
        As[akv + 3][row] = pa[r].w;
        *(float4*)&Bs[brow + 8 * r][bcv] = pb[r];
    }
    __syncthreads();

    for (int k0 = 0; k0 < IN_DIM; k0 += BK) {
        const bool has_next = (k0 + BK) < IN_DIM;
        if (has_next) {
#pragma unroll
            for (int r = 0; r < 4; r++) {
                int row = arow + 32 * r;
                int gr = bm + row;
                pa[r] = make_float4(0.f, 0.f, 0.f, 0.f);
                if (gr < N_NODES)
                    pa[r] = *(const float4*)&x[(size_t)gr * IN_DIM + k0 + BK + akv];
                pb[r] = *(const float4*)&W[(size_t)(k0 + BK + brow + 8 * r) * F1 + bn + bcv];
            }
        }
#pragma unroll
        for (int kk = 0; kk < BK; kk++) {
            ulonglong2 bv0 = *(const ulonglong2*)&Bs[kk][tx * 8];
            ulonglong2 bv1 = *(const ulonglong2*)&Bs[kk][tx * 8 + 4];
            float4 a0 = *(const float4*)&As[kk][ty * 8];
            float4 a1 = *(const float4*)&As[kk][ty * 8 + 4];
            float a[8] = {a0.x, a0.y, a0.z, a0.w, a1.x, a1.y, a1.z, a1.w};
#pragma unroll
            for (int i = 0; i < 8; i++) {
                unsigned long long aa = pk2(a[i], a[i]);
                fma2(acc[i][0], aa, bv0.x);
                fma2(acc[i][1], aa, bv0.y);
                fma2(acc[i][2], aa, bv1.x);
                fma2(acc[i][3], aa, bv1.y);
            }
        }
        if (has_next) {
            __syncthreads();   // all warps done reading current tile
#pragma unroll
            for (int r = 0; r < 4; r++) {
                int row = arow + 32 * r;
                As[akv + 0][row] = pa[r].x;
                As[akv + 1][row] = pa[r].y;
                As[akv + 2][row] = pa[r].z;
                As[akv + 3][row] = pa[r].w;
                *(float4*)&Bs[brow + 8 * r][bcv] = pb[r];
            }
            __syncthreads();   // new tile visible
        }
    }

    // epilogue: store h1 + fused attention partial dots.
    // 8 consecutive lanes = 8 distinct tx sharing ty -> one 64-col head.
    const int col0 = bn + tx * 8;
    const int head = col0 >> 6;
    float avS[8], avD[8];
#pragma unroll
    for (int j = 0; j < 8; j++) { avS[j] = atts[col0 + j]; avD[j] = attd[col0 + j]; }

#pragma unroll
    for (int i = 0; i < 8; i++) {
        int gr = bm + ty * 8 + i;
        float2 c0 = upk2(acc[i][0]), c1 = upk2(acc[i][1]);
        float2 c2 = upk2(acc[i][2]), c3 = upk2(acc[i][3]);
        float cv[8] = {c0.x, c0.y, c1.x, c1.y, c2.x, c2.y, c3.x, c3.y};
        if (gr < N_NODES) {
            *(float4*)&g_h1[(size_t)gr * F1 + col0]     = make_float4(cv[0], cv[1], cv[2], cv[3]);
            *(float4*)&g_h1[(size_t)gr * F1 + col0 + 4] = make_float4(cv[4], cv[5], cv[6], cv[7]);
        }
        float ps = 0.f, pd = 0.f;
#pragma unroll
        for (int j = 0; j < 8; j++) {
            ps = fmaf(cv[j], avS[j], ps);
            pd = fmaf(cv[j], avD[j], pd);
        }
#pragma unroll
        for (int off = 4; off; off >>= 1) {
            ps += __shfl_down_sync(0xffffffffu, ps, off, 8);
            pd += __shfl_down_sync(0xffffffffu, pd, off, 8);
        }
        if ((l & 7) == 0 && gr < N_NODES) {
            atomicAdd(&g_as1[gr * 4 + head], ps);
            atomicAdd(&g_ad1[gr * 4 + head], pd);
        }
    }
}

// ---------------- layer-1 aggregation: WARP per node ----------------
__global__ __launch_bounds__(256) void k_agg1w(const float* __restrict__ b1) {
    const int node = blockIdx.x * 8 + (threadIdx.x >> 5);  // 6250*8 = 50000 exact
    const int lane = threadIdx.x & 31;
    const int start = g_rowstart[node];
    const int cnt = g_rowstart[node + 1] - start;

    float4 adv = *(const float4*)&g_ad1[node * 4];

    float m0 = NINF, m1 = NINF, m2 = NINF, m3 = NINF;
    for (int e = lane; e < cnt; e += 32) {
        int s = g_csr[start + e];
        float4 av = *(const float4*)&g_as1[s * 4];
        m0 = fmaxf(m0, lrelu(av.x + adv.x));
        m1 = fmaxf(m1, lrelu(av.y + adv.y));
        m2 = fmaxf(m2, lrelu(av.z + adv.z));
        m3 = fmaxf(m3, lrelu(av.w + adv.w));
    }
#pragma unroll
    for (int off = 16; off; off >>= 1) {
        m0 = fmaxf(m0, __shfl_xor_sync(0xffffffffu, m0, off));
        m1 = fmaxf(m1, __shfl_xor_sync(0xffffffffu, m1, off));
        m2 = fmaxf(m2, __shfl_xor_sync(0xffffffffu, m2, off));
        m3 = fmaxf(m3, __shfl_xor_sync(0xffffffffu, m3, off));
    }

    float s0 = 0.f, s1 = 0.f, s2 = 0.f, s3 = 0.f;
    for (int e = lane; e < cnt; e += 32) {
        int s = g_csr[start + e];
        float4 av = *(const float4*)&g_as1[s * 4];
        s0 += expf(lrelu(av.x + adv.x) - m0);
        s1 += expf(lrelu(av.y + adv.y) - m1);
        s2 += expf(lrelu(av.z + adv.z) - m2);
        s3 += expf(lrelu(av.w + adv.w) - m3);
    }
#pragma unroll
    for (int off = 16; off; off >>= 1) {
        s0 += __shfl_xor_sync(0xffffffffu, s0, off);
        s1 += __shfl_xor_sync(0xffffffffu, s1, off);
        s2 += __shfl_xor_sync(0xffffffffu, s2, off);
        s3 += __shfl_xor_sync(0xffffffffu, s3, off);
    }

    const int hh = lane >> 3;
    float advh = (hh == 0) ? adv.x : (hh == 1) ? adv.y : (hh == 2) ? adv.z : adv.w;
    float mh   = (hh == 0) ? m0    : (hh == 1) ? m1    : (hh == 2) ? m2    : m3;
    float sumh = (hh == 0) ? s0    : (hh == 1) ? s1    : (hh == 2) ? s2    : s3;
    const float invh = 1.f / (sumh + 1e-16f);

    float4 a0 = make_float4(0.f, 0.f, 0.f, 0.f);
    float4 a1 = make_float4(0.f, 0.f, 0.f, 0.f);
    const int coff = lane * 8;
    for (int e = 0; e < cnt; e++) {
        int s = g_csr[start + e];
        float av = __ldg(&g_as1[s * 4 + hh]);
        float al = expf(lrelu(av + advh) - mh) * invh;
        const float* row = &g_h1[(size_t)s * F1 + coff];
        float4 v0 = *(const float4*)row;
        float4 v1 = *(const float4*)(row + 4);
        a0.x = fmaf(al, v0.x, a0.x); a0.y = fmaf(al, v0.y, a0.y);
        a0.z = fmaf(al, v0.z, a0.z); a0.w = fmaf(al, v0.w, a0.w);
        a1.x = fmaf(al, v1.x, a1.x); a1.y = fmaf(al, v1.y, a1.y);
        a1.z = fmaf(al, v1.z, a1.z); a1.w = fmaf(al, v1.w, a1.w);
    }

    float4 bb0 = *(const float4*)&b1[coff];
    float4 bb1 = *(const float4*)&b1[coff + 4];
    float r0 = a0.x + bb0.x, r1 = a0.y + bb0.y, r2 = a0.z + bb0.z, r3 = a0.w + bb0.w;
    float r4 = a1.x + bb1.x, r5 = a1.y + bb1.y, r6 = a1.z + bb1.z, r7 = a1.w + bb1.w;
    r0 = r0 > 0.f ? r0 : expm1f(r0); r1 = r1 > 0.f ? r1 : expm1f(r1);
    r2 = r2 > 0.f ? r2 : expm1f(r2); r3 = r3 > 0.f ? r3 : expm1f(r3);
    r4 = r4 > 0.f ? r4 : expm1f(r4); r5 = r5 > 0.f ? r5 : expm1f(r5);
    r6 = r6 > 0.f ? r6 : expm1f(r6); r7 = r7 > 0.f ? r7 : expm1f(r7);
    float* orow = &g_hmid[(size_t)node * F1 + coff];
    *(float4*)orow       = make_float4(r0, r1, r2, r3);
    *(float4*)(orow + 4) = make_float4(r4, r5, r6, r7);
}

// ---------------- GEMM2 + fused attention dots (transposed A, conflict-free) ----
#define BM2 128
#define BK2 32
#define A2PAD 132
__global__ __launch_bounds__(256) void k_gemm2(const float* __restrict__ W2,
                                               const float* __restrict__ atts,
                                               const float* __restrict__ attd) {
    __shared__ __align__(16) float As2t[BK2][A2PAD];
    __shared__ __align__(16) float Ws[BK2][F2];
    const int bm = blockIdx.x * BM2;
    const int t = threadIdx.x;
    const int tx = t & 7;
    const int ty = t >> 3;
    float acc[4][5];
#pragma unroll
    for (int i = 0; i < 4; i++)
#pragma unroll
        for (int j = 0; j < 5; j++) acc[i][j] = 0.f;

    for (int k0 = 0; k0 < F1; k0 += BK2) {
#pragma unroll
        for (int r = 0; r < 4; r++) {
            int f = t + r * 256;
            int row = f >> 3;
            int cv = (f & 7) * 4;
            float4 v = make_float4(0.f, 0.f, 0.f, 0.f);
            int gr = bm + row;
            if (gr < N_NODES) v = *(const float4*)&g_hmid[(size_t)gr * F1 + k0 + cv];
            As2t[cv + 0][row] = v.x;
            As2t[cv + 1][row] = v.y;
            As2t[cv + 2][row] = v.z;
            As2t[cv + 3][row] = v.w;
        }
        for (int idx = t; idx < BK2 * F2; idx += 256) {
            int r = idx / F2, c = idx % F2;
            Ws[r][c] = W2[(size_t)(k0 + r) * F2 + c];
        }
        __syncthreads();
#pragma unroll
        for (int kk = 0; kk < BK2; kk++) {
            float4 a4 = *(const float4*)&As2t[kk][ty * 4];
            float a[4] = {a4.x, a4.y, a4.z, a4.w};
            float b[5];
#pragma unroll
            for (int j = 0; j < 5; j++) b[j] = Ws[kk][tx * 5 + j];
#pragma unroll
            for (int i = 0; i < 4; i++)
#pragma unroll
                for (int j = 0; j < 5; j++) acc[i][j] = fmaf(a[i], b[j], acc[i][j]);
        }
        __syncthreads();
    }

    float avS[5], avD[5];
#pragma unroll
    for (int j = 0; j < 5; j++) { avS[j] = atts[tx * 5 + j]; avD[j] = attd[tx * 5 + j]; }
#pragma unroll
    for (int i = 0; i < 4; i++) {
        int gr = bm + ty * 4 + i;
        if (gr < N_NODES)
#pragma unroll
            for (int j = 0; j < 5; j++)
                g_h2[(size_t)gr * F2 + tx * 5 + j] = acc[i][j];
        float ps = 0.f, pd = 0.f;
#pragma unroll
        for (int j = 0; j < 5; j++) {
            ps = fmaf(acc[i][j], avS[j], ps);
            pd = fmaf(acc[i][j], avD[j], pd);
        }
#pragma unroll
        for (int off = 4; off; off >>= 1) {
            ps += __shfl_down_sync(0xffffffffu, ps, off, 8);
            pd += __shfl_down_sync(0xffffffffu, pd, off, 8);
        }
        if (tx == 0 && gr < N_NODES) { g_as2[gr] = ps; g_ad2[gr] = pd; }
    }
}

// ---------------- layer-2 aggregation + log_softmax: WARP per node ----------------
__global__ __launch_bounds__(256) void k_agg2w(const float* __restrict__ b2,
                                               float* __restrict__ out) {
    const int node = blockIdx.x * 8 + (threadIdx.x >> 5);
    const int lane = threadIdx.x & 31;
    const int start = g_rowstart[node];
    const int cnt = g_rowstart[node + 1] - start;
    const float adv = g_ad2[node];

    float m = NINF;
    for (int e = lane; e < cnt; e += 32)
        m = fmaxf(m, lrelu(g_as2[g_csr[start + e]] + adv));
#pragma unroll
    for (int off = 16; off; off >>= 1)
        m = fmaxf(m, __shfl_xor_sync(0xffffffffu, m, off));

    float se = 0.f;
    for (int e = lane; e < cnt; e += 32)
        se += expf(lrelu(g_as2[g_csr[start + e]] + adv) - m);
#pragma unroll
    for (int off = 16; off; off >>= 1)
        se += __shfl_xor_sync(0xffffffffu, se, off);
    const float inv = 1.f / (se + 1e-16f);

    float a0 = 0.f, a1 = 0.f;
    for (int e = 0; e < cnt; e++) {
        int s = g_csr[start + e];
        float al = expf(lrelu(__ldg(&g_as2[s]) + adv) - m) * inv;
        const float* row = &g_h2[(size_t)s * F2];
        a0 = fmaf(al, row[lane], a0);
        if (lane < 8) a1 = fmaf(al, row[32 + lane], a1);
    }
    float v0 = a0 + b2[lane];
    float v1 = (lane < 8) ? (a1 + b2[32 + lane]) : NINF;

    float mm = fmaxf(v0, v1);
#pragma unroll
    for (int off = 16; off; off >>= 1)
        mm = fmaxf(mm, __shfl_xor_sync(0xffffffffu, mm, off));
    float s2 = expf(v0 - mm) + ((lane < 8) ? expf(v1 - mm) : 0.f);
#pragma unroll
    for (int off = 16; off; off >>= 1)
        s2 += __shfl_xor_sync(0xffffffffu, s2, off);
    const float lg = logf(s2);

    float* orow = &out[(size_t)node * F2];
    orow[lane] = v0 - mm - lg;
    if (lane < 8) orow[32 + lane] = v1 - mm - lg;
}

// ---------------- launch ----------------
extern "C" void kernel_launch(void* const* d_in, const int* in_sizes, int n_in,
                              void* d_out, int out_size) {
    const float* x   = (const float*)d_in[0];
    const void*  ei  = d_in[1];
    const float* W1  = (const float*)d_in[2];
    const float* as1 = (const float*)d_in[3];
    const float* ad1 = (const float*)d_in[4];
    const float* b1  = (const float*)d_in[5];
    const float* W2  = (const float*)d_in[6];
    const float* as2 = (const float*)d_in[7];
    const float* ad2 = (const float*)d_in[8];
    const float* b2  = (const float*)d_in[9];
    float* out = (float*)d_out;

    k_init<<<SCAN_BLOCKS, 256>>>((const int*)ei);            // #1
    k_convert_count<<<(E_EDGES + 255) / 256, 256>>>(ei);     // #2
    k_bsum<<<SCAN_BLOCKS, 256>>>();                          // #3
    dim3 g1(F1 / BN, (N_NODES + BM - 1) / BM);
    k_gemm1<<<g1, 256>>>(x, W1, as1, ad1);                   // #4  <- profiled
    k_rowstart2<<<SCAN_BLOCKS, 256>>>();                     // #5
    k_scatter<<<(E_TOT + 255) / 256, 256>>>();               // #6
    k_agg1w<<<N_NODES / 8, 256>>>(b1);                       // #7
    k_gemm2<<<(N_NODES + BM2 - 1) / BM2, 256>>>(W2, as2, ad2);  // #8
    k_agg2w<<<N_NODES / 8, 256>>>(b2, out);                  // #9
}

// round 14
// speedup vs baseline: 1.5890x; 1.2930x over previous
#include <cuda_runtime.h>
#include <cuda_bf16.h>
#include <math.h>
#include <stdint.h>

#define N_NODES 50000
#define E_EDGES 800000
#define E_TOT   (E_EDGES + N_NODES)
#define IN_DIM  512
#define F1      256
#define NH1     4
#define F2      40
#define NEG_SLOPE 0.2f
#define NINF (-__int_as_float(0x7f800000))
#define SCAN_BLOCKS 196

// ---------------- scratch ----------------
__device__ int   g_is64;
__device__ int   g_src[E_EDGES];
__device__ int   g_dst[E_EDGES];
__device__ int   g_deg[N_NODES];
__device__ int   g_bsum[SCAN_BLOCKS];
__device__ int   g_rowstart[N_NODES + 1];
__device__ int   g_cursor[N_NODES];
__device__ int   g_csr[E_TOT];
__device__ __align__(16) float g_h1[(size_t)N_NODES * F1];
__device__ __align__(16) float g_as1[N_NODES * NH1];
__device__ __align__(16) float g_ad1[N_NODES * NH1];
__device__ __align__(16) float g_hmid[(size_t)N_NODES * F1];
__device__ __align__(16) float g_h2[(size_t)N_NODES * F2];
__device__ float g_as2[N_NODES];
__device__ float g_ad2[N_NODES];
// bf16 split W1, transposed to [n][k]
__device__ __align__(16) __nv_bfloat16 g_wt1[(size_t)F1 * IN_DIM];
__device__ __align__(16) __nv_bfloat16 g_wt2[(size_t)F1 * IN_DIM];

// ---------------- helpers ----------------
__device__ __forceinline__ float lrelu(float x) { return x > 0.f ? x : NEG_SLOPE * x; }

__device__ __forceinline__ uint32_t smem_u32(const void* p) {
    uint32_t a;
    asm("{ .reg .u64 t; cvta.to.shared.u64 t, %1; cvt.u32.u64 %0, t; }" : "=r"(a) : "l"(p));
    return a;
}

#define LDSM_X4(r, a) \
    asm volatile("ldmatrix.sync.aligned.m8n8.x4.shared.b16 {%0,%1,%2,%3}, [%4];" \
        : "=r"((r)[0]), "=r"((r)[1]), "=r"((r)[2]), "=r"((r)[3]) : "r"(a))

#define MMA_BF16(c, a, b0, b1) \
    asm volatile("mma.sync.aligned.m16n8k16.row.col.f32.bf16.bf16.f32 " \
        "{%0,%1,%2,%3}, {%4,%5,%6,%7}, {%8,%9}, {%0,%1,%2,%3};" \
        : "+f"((c)[0]), "+f"((c)[1]), "+f"((c)[2]), "+f"((c)[3]) \
        : "r"((a)[0]), "r"((a)[1]), "r"((a)[2]), "r"((a)[3]), "r"(b0), "r"(b1))

// ---------------- init ----------------
__global__ void k_init(const int* e32) {
    int i = blockIdx.x * blockDim.x + threadIdx.x;
    if (i < N_NODES) g_deg[i] = 1;
    if (i == 0) {
        int allzero = 1;
        for (int j = 1; j < 256; j += 2) if (e32[j] != 0) allzero = 0;
        g_is64 = allzero;
    }
}

__global__ void k_convert_count(const void* eptr) {
    int i = blockIdx.x * blockDim.x + threadIdx.x;
    if (i >= E_EDGES) return;
    int s, d;
    if (g_is64) {
        const long long* e = (const long long*)eptr;
        s = (int)e[i];
        d = (int)e[E_EDGES + i];
    } else {
        const int* e = (const int*)eptr;
        s = e[i];
        d = e[E_EDGES + i];
    }
    g_src[i] = s;
    g_dst[i] = d;
    atomicAdd(&g_deg[d], 1);
}

// ---------------- W1 transpose + bf16 split (tiled) ----------------
__global__ void k_split_w(const float* __restrict__ W) {
    __shared__ float tile[32][33];
    const int t = threadIdx.x;
    const int tx = t & 31, ty = t >> 5;
    const int k0 = (blockIdx.x & 15) * 32;
    const int n0 = (blockIdx.x >> 4) * 32;
#pragma unroll
    for (int i = 0; i < 4; i++)
        tile[ty * 4 + i][tx] = W[(size_t)(k0 + ty * 4 + i) * F1 + n0 + tx];
    __syncthreads();
#pragma unroll
    for (int i = 0; i < 4; i++) {
        int n = n0 + ty * 4 + i;
        float v = tile[tx][ty * 4 + i];
        __nv_bfloat16 h = __float2bfloat16(v);
        g_wt1[(size_t)n * IN_DIM + k0 + tx] = h;
        g_wt2[(size_t)n * IN_DIM + k0 + tx] = __float2bfloat16(v - __bfloat162float(h));
    }
}

// ---------------- CSR scan ----------------
__global__ void k_bsum() {
    __shared__ int sh[256];
    const int b = blockIdx.x, t = threadIdx.x;
    const int i = b * 256 + t;
    sh[t] = (i < N_NODES) ? g_deg[i] : 0;
    __syncthreads();
#pragma unroll
    for (int off = 128; off; off >>= 1) {
        if (t < off) sh[t] += sh[t + off];
        __syncthreads();
    }
    if (t == 0) g_bsum[b] = sh[0];
}

__global__ void k_rowstart2() {
    __shared__ int sred[256];
    __shared__ int sh[256];
    const int b = blockIdx.x, t = threadIdx.x;
    sred[t] = (t < b) ? g_bsum[t] : 0;
    __syncthreads();
#pragma unroll
    for (int off = 128; off; off >>= 1) {
        if (t < off) sred[t] += sred[t + off];
        __syncthreads();
    }
    const int boff = sred[0];
    const int i = b * 256 + t;
    const int v = (i < N_NODES) ? g_deg[i] : 0;
    sh[t] = v;
    __syncthreads();
#pragma unroll
    for (int off = 1; off < 256; off <<= 1) {
        int u = (t >= off) ? sh[t - off] : 0;
        __syncthreads();
        sh[t] += u;
        __syncthreads();
    }
    const int excl = boff + sh[t] - v;
    if (i < N_NODES) {
        g_rowstart[i] = excl;
        g_cursor[i]   = excl;
        if (i == N_NODES - 1) g_rowstart[N_NODES] = excl + v;
    }
}

__global__ void k_scatter() {
    int i = blockIdx.x * blockDim.x + threadIdx.x;
    if (i >= E_TOT) return;
    int s, d;
    if (i < E_EDGES) { s = g_src[i]; d = g_dst[i]; }
    else             { s = d = i - E_EDGES; }
    int pos = atomicAdd(&g_cursor[d], 1);
    g_csr[pos] = s;
}

// ---------------- GEMM1 via HMMA (mma.sync bf16 split) + fused attention dots --
#define STRIDE_B 112
#define T1_A1 0
#define T1_A2 14336
#define T1_B1 28672
#define T1_B2 43008
#define T1_SA 57344
#define T1_SD 57856
#define T1_TOTAL 58368

__global__ __launch_bounds__(256) void k_gemm1h(const float* __restrict__ x,
                                                const float* __restrict__ atts,
                                                const float* __restrict__ attd) {
    extern __shared__ __align__(16) char smem[];
    const uint32_t sb = smem_u32(smem);
    const int t = threadIdx.x;
    const int wid = t >> 5, lane = t & 31;
    const int bm = blockIdx.y * 128;
    const int bn = blockIdx.x * 128;
    const int wm = (wid & 3) * 32;
    const int wn = (wid >> 2) * 64;

    if (t < 128) {
        ((float*)(smem + T1_SA))[t] = atts[bn + t];
        ((float*)(smem + T1_SD))[t] = attd[bn + t];
    }

    float acc[2][8][4];
#pragma unroll
    for (int mi = 0; mi < 2; mi++)
#pragma unroll
        for (int ni = 0; ni < 8; ni++)
#pragma unroll
            for (int q = 0; q < 4; q++) acc[mi][ni][q] = 0.f;

    // ldmatrix lane address components
    const int lr = lane & 7;
    const int aRow = lr + 8 * ((lane >> 3) & 1);   // A regs: {m0k0, m8k0, m0k8, m8k8}
    const int aKk  = 8 * (lane >> 4);
    const int bRow = lr + 8 * (lane >> 4);         // B regs: {n0k0, n0k8, n8k0, n8k8}  (FIXED: was 16*)
    const int bKk  = 8 * ((lane >> 3) & 1);

    for (int c = 0; c < IN_DIM / 32; c++) {
        const int k0 = c * 32;
        __syncthreads();
        // stage A: fp32 -> bf16 hi/lo, 128 rows x 32 k
#pragma unroll
        for (int q = 0; q < 4; q++) {
            int f = t + q * 256;
            int row = f >> 3, jc = (f & 7) * 4;
            float4 v = make_float4(0.f, 0.f, 0.f, 0.f);
            int gr = bm + row;
            if (gr < N_NODES) v = *(const float4*)&x[(size_t)gr * IN_DIM + k0 + jc];
            __nv_bfloat16 h0 = __float2bfloat16(v.x), h1 = __float2bfloat16(v.y);
            __nv_bfloat16 h2 = __float2bfloat16(v.z), h3 = __float2bfloat16(v.w);
            __nv_bfloat16 l0 = __float2bfloat16(v.x - __bfloat162float(h0));
            __nv_bfloat16 l1 = __float2bfloat16(v.y - __bfloat162float(h1));
            __nv_bfloat16 l2 = __float2bfloat16(v.z - __bfloat162float(h2));
            __nv_bfloat16 l3 = __float2bfloat16(v.w - __bfloat162float(h3));
            uint2 hi, lo;
            hi.x = (uint32_t)__bfloat16_as_ushort(h0) | ((uint32_t)__bfloat16_as_ushort(h1) << 16);
            hi.y = (uint32_t)__bfloat16_as_ushort(h2) | ((uint32_t)__bfloat16_as_ushort(h3) << 16);
            lo.x = (uint32_t)__bfloat16_as_ushort(l0) | ((uint32_t)__bfloat16_as_ushort(l1) << 16);
            lo.y = (uint32_t)__bfloat16_as_ushort(l2) | ((uint32_t)__bfloat16_as_ushort(l3) << 16);
            *(uint2*)(smem + T1_A1 + row * STRIDE_B + jc * 2) = hi;
            *(uint2*)(smem + T1_A2 + row * STRIDE_B + jc * 2) = lo;
        }
        // stage B: pre-split bf16 [n][k]
#pragma unroll
        for (int q = 0; q < 2; q++) {
            int f = t + q * 256;
            int row = f >> 2, jc = (f & 3) * 8;
            uint4 b1 = *(const uint4*)(g_wt1 + (size_t)(bn + row) * IN_DIM + k0 + jc);
            uint4 b2 = *(const uint4*)(g_wt2 + (size_t)(bn + row) * IN_DIM + k0 + jc);
            *(uint4*)(smem + T1_B1 + row * STRIDE_B + jc * 2) = b1;
            *(uint4*)(smem + T1_B2 + row * STRIDE_B + jc * 2) = b2;
        }
        __syncthreads();

#pragma unroll
        for (int ks = 0; ks < 32; ks += 16) {
            uint32_t a1f[2][4], a2f[2][4];
#pragma unroll
            for (int mi = 0; mi < 2; mi++) {
                uint32_t off = (uint32_t)((wm + mi * 16 + aRow) * STRIDE_B + (ks + aKk) * 2);
                LDSM_X4(a1f[mi], sb + T1_A1 + off);
                LDSM_X4(a2f[mi], sb + T1_A2 + off);
            }
#pragma unroll
            for (int njp = 0; njp < 4; njp++) {
                uint32_t b1f[4], b2f[4];
                uint32_t off = (uint32_t)((wn + njp * 16 + bRow) * STRIDE_B + (ks + bKk) * 2);
                LDSM_X4(b1f, sb + T1_B1 + off);
                LDSM_X4(b2f, sb + T1_B2 + off);
#pragma unroll
                for (int h = 0; h < 2; h++) {
                    int ni = njp * 2 + h;
#pragma unroll
                    for (int mi = 0; mi < 2; mi++) {
                        MMA_BF16(acc[mi][ni], a1f[mi], b1f[2 * h], b1f[2 * h + 1]);
                        MMA_BF16(acc[mi][ni], a1f[mi], b2f[2 * h], b2f[2 * h + 1]);
                        MMA_BF16(acc[mi][ni], a2f[mi], b1f[2 * h], b1f[2 * h + 1]);
                    }
                }
            }
        }
    }

    // epilogue: store h1 + direct attention-dot stores (warp owns one head)
    const int group = lane >> 2, qt = lane & 3;
    const float* sa = (const float*)(smem + T1_SA);
    const float* sd = (const float*)(smem + T1_SD);
    const int head = (bn >> 6) + (wn >> 6);
#pragma unroll
    for (int mi = 0; mi < 2; mi++) {
#pragma unroll
        for (int hr = 0; hr < 2; hr++) {
            int r = bm + wm + mi * 16 + group + hr * 8;
            float ps = 0.f, pd = 0.f;
            if (r < N_NODES) {
#pragma unroll
                for (int ni = 0; ni < 8; ni++) {
                    float v0 = acc[mi][ni][hr * 2], v1 = acc[mi][ni][hr * 2 + 1];
                    int cl = wn + ni * 8 + qt * 2;
                    *(float2*)&g_h1[(size_t)r * F1 + bn + cl] = make_float2(v0, v1);
                    ps = fmaf(v0, sa[cl], ps); ps = fmaf(v1, sa[cl + 1], ps);
                    pd = fmaf(v0, sd[cl], pd); pd = fmaf(v1, sd[cl + 1], pd);
                }
            }
            ps += __shfl_xor_sync(0xffffffffu, ps, 1);
            ps += __shfl_xor_sync(0xffffffffu, ps, 2);
            pd += __shfl_xor_sync(0xffffffffu, pd, 1);
            pd += __shfl_xor_sync(0xffffffffu, pd, 2);
            if (qt == 0 && r < N_NODES) {
                g_as1[r * 4 + head] = ps;
                g_ad1[r * 4 + head] = pd;
            }
        }
    }
}

// ---------------- layer-1 aggregation: WARP per node ----------------
__global__ __launch_bounds__(256) void k_agg1w(const float* __restrict__ b1) {
    const int node = blockIdx.x * 8 + (threadIdx.x >> 5);
    const int lane = threadIdx.x & 31;
    const int start = g_rowstart[node];
    const int cnt = g_rowstart[node + 1] - start;

    float4 adv = *(const float4*)&g_ad1[node * 4];

    float m0 = NINF, m1 = NINF, m2 = NINF, m3 = NINF;
    for (int e = lane; e < cnt; e += 32) {
        int s = g_csr[start + e];
        float4 av = *(const float4*)&g_as1[s * 4];
        m0 = fmaxf(m0, lrelu(av.x + adv.x));
        m1 = fmaxf(m1, lrelu(av.y + adv.y));
        m2 = fmaxf(m2, lrelu(av.z + adv.z));
        m3 = fmaxf(m3, lrelu(av.w + adv.w));
    }
#pragma unroll
    for (int off = 16; off; off >>= 1) {
        m0 = fmaxf(m0, __shfl_xor_sync(0xffffffffu, m0, off));
        m1 = fmaxf(m1, __shfl_xor_sync(0xffffffffu, m1, off));
        m2 = fmaxf(m2, __shfl_xor_sync(0xffffffffu, m2, off));
        m3 = fmaxf(m3, __shfl_xor_sync(0xffffffffu, m3, off));
    }

    float s0 = 0.f, s1 = 0.f, s2 = 0.f, s3 = 0.f;
    for (int e = lane; e < cnt; e += 32) {
        int s = g_csr[start + e];
        float4 av = *(const float4*)&g_as1[s * 4];
        s0 += expf(lrelu(av.x + adv.x) - m0);
        s1 += expf(lrelu(av.y + adv.y) - m1);
        s2 += expf(lrelu(av.z + adv.z) - m2);
        s3 += expf(lrelu(av.w + adv.w) - m3);
    }
#pragma unroll
    for (int off = 16; off; off >>= 1) {
        s0 += __shfl_xor_sync(0xffffffffu, s0, off);
        s1 += __shfl_xor_sync(0xffffffffu, s1, off);
        s2 += __shfl_xor_sync(0xffffffffu, s2, off);
        s3 += __shfl_xor_sync(0xffffffffu, s3, off);
    }

    const int hh = lane >> 3;
    float advh = (hh == 0) ? adv.x : (hh == 1) ? adv.y : (hh == 2) ? adv.z : adv.w;
    float mh   = (hh == 0) ? m0    : (hh == 1) ? m1    : (hh == 2) ? m2    : m3;
    float sumh = (hh == 0) ? s0    : (hh == 1) ? s1    : (hh == 2) ? s2    : s3;
    const float invh = 1.f / (sumh + 1e-16f);

    float4 a0 = make_float4(0.f, 0.f, 0.f, 0.f);
    float4 a1 = make_float4(0.f, 0.f, 0.f, 0.f);
    const int coff = lane * 8;
    for (int e = 0; e < cnt; e++) {
        int s = g_csr[start + e];
        float av = __ldg(&g_as1[s * 4 + hh]);
        float al = expf(lrelu(av + advh) - mh) * invh;
        const float* row = &g_h1[(size_t)s * F1 + coff];
        float4 v0 = *(const float4*)row;
        float4 v1 = *(const float4*)(row + 4);
        a0.x = fmaf(al, v0.x, a0.x); a0.y = fmaf(al, v0.y, a0.y);
        a0.z = fmaf(al, v0.z, a0.z); a0.w = fmaf(al, v0.w, a0.w);
        a1.x = fmaf(al, v1.x, a1.x); a1.y = fmaf(al, v1.y, a1.y);
        a1.z = fmaf(al, v1.z, a1.z); a1.w = fmaf(al, v1.w, a1.w);
    }

    float4 bb0 = *(const float4*)&b1[coff];
    float4 bb1 = *(const float4*)&b1[coff + 4];
    float r0 = a0.x + bb0.x, r1 = a0.y + bb0.y, r2 = a0.z + bb0.z, r3 = a0.w + bb0.w;
    float r4 = a1.x + bb1.x, r5 = a1.y + bb1.y, r6 = a1.z + bb1.z, r7 = a1.w + bb1.w;
    r0 = r0 > 0.f ? r0 : expm1f(r0); r1 = r1 > 0.f ? r1 : expm1f(r1);
    r2 = r2 > 0.f ? r2 : expm1f(r2); r3 = r3 > 0.f ? r3 : expm1f(r3);
    r4 = r4 > 0.f ? r4 : expm1f(r4); r5 = r5 > 0.f ? r5 : expm1f(r5);
    r6 = r6 > 0.f ? r6 : expm1f(r6); r7 = r7 > 0.f ? r7 : expm1f(r7);
    float* orow = &g_hmid[(size_t)node * F1 + coff];
    *(float4*)orow       = make_float4(r0, r1, r2, r3);
    *(float4*)(orow + 4) = make_float4(r4, r5, r6, r7);
}

// ---------------- GEMM2 + fused attention dots ----------------
#define BM2 128
#define BK2 32
#define A2PAD 132
__global__ __launch_bounds__(256) void k_gemm2(const float* __restrict__ W2,
                                               const float* __restrict__ atts,
                                               const float* __restrict__ attd) {
    __shared__ __align__(16) float As2t[BK2][A2PAD];
    __shared__ __align__(16) float Ws[BK2][F2];
    const int bm = blockIdx.x * BM2;
    const int t = threadIdx.x;
    const int tx = t & 7;
    const int ty = t >> 3;
    float acc[4][5];
#pragma unroll
    for (int i = 0; i < 4; i++)
#pragma unroll
        for (int j = 0; j < 5; j++) acc[i][j] = 0.f;

    for (int k0 = 0; k0 < F1; k0 += BK2) {
#pragma unroll
        for (int r = 0; r < 4; r++) {
            int f = t + r * 256;
            int row = f >> 3;
            int cv = (f & 7) * 4;
            float4 v = make_float4(0.f, 0.f, 0.f, 0.f);
            int gr = bm + row;
            if (gr < N_NODES) v = *(const float4*)&g_hmid[(size_t)gr * F1 + k0 + cv];
            As2t[cv + 0][row] = v.x;
            As2t[cv + 1][row] = v.y;
            As2t[cv + 2][row] = v.z;
            As2t[cv + 3][row] = v.w;
        }
        for (int idx = t; idx < BK2 * F2; idx += 256) {
            int r = idx / F2, c = idx % F2;
            Ws[r][c] = W2[(size_t)(k0 + r) * F2 + c];
        }
        __syncthreads();
#pragma unroll
        for (int kk = 0; kk < BK2; kk++) {
            float4 a4 = *(const float4*)&As2t[kk][ty * 4];
            float a[4] = {a4.x, a4.y, a4.z, a4.w};
            float b[5];
#pragma unroll
            for (int j = 0; j < 5; j++) b[j] = Ws[kk][tx * 5 + j];
#pragma unroll
            for (int i = 0; i < 4; i++)
#pragma unroll
                for (int j = 0; j < 5; j++) acc[i][j] = fmaf(a[i], b[j], acc[i][j]);
        }
        __syncthreads();
    }

    float avS[5], avD[5];
#pragma unroll
    for (int j = 0; j < 5; j++) { avS[j] = atts[tx * 5 + j]; avD[j] = attd[tx * 5 + j]; }
#pragma unroll
    for (int i = 0; i < 4; i++) {
        int gr = bm + ty * 4 + i;
        if (gr < N_NODES)
#pragma unroll
            for (int j = 0; j < 5; j++)
                g_h2[(size_t)gr * F2 + tx * 5 + j] = acc[i][j];
        float ps = 0.f, pd = 0.f;
#pragma unroll
        for (int j = 0; j < 5; j++) {
            ps = fmaf(acc[i][j], avS[j], ps);
            pd = fmaf(acc[i][j], avD[j], pd);
        }
#pragma unroll
        for (int off = 4; off; off >>= 1) {
            ps += __shfl_down_sync(0xffffffffu, ps, off, 8);
            pd += __shfl_down_sync(0xffffffffu, pd, off, 8);
        }
        if (tx == 0 && gr < N_NODES) { g_as2[gr] = ps; g_ad2[gr] = pd; }
    }
}

// ---------------- layer-2 aggregation + log_softmax: WARP per node ----------------
__global__ __launch_bounds__(256) void k_agg2w(const float* __restrict__ b2,
                                               float* __restrict__ out) {
    const int node = blockIdx.x * 8 + (threadIdx.x >> 5);
    const int lane = threadIdx.x & 31;
    const int start = g_rowstart[node];
    const int cnt = g_rowstart[node + 1] - start;
    const float adv = g_ad2[node];

    float m = NINF;
    for (int e = lane; e < cnt; e += 32)
        m = fmaxf(m, lrelu(g_as2[g_csr[start + e]] + adv));
#pragma unroll
    for (int off = 16; off; off >>= 1)
        m = fmaxf(m, __shfl_xor_sync(0xffffffffu, m, off));

    float se = 0.f;
    for (int e = lane; e < cnt; e += 32)
        se += expf(lrelu(g_as2[g_csr[start + e]] + adv) - m);
#pragma unroll
    for (int off = 16; off; off >>= 1)
        se += __shfl_xor_sync(0xffffffffu, se, off);
    const float inv = 1.f / (se + 1e-16f);

    float a0 = 0.f, a1 = 0.f;
    for (int e = 0; e < cnt; e++) {
        int s = g_csr[start + e];
        float al = expf(lrelu(__ldg(&g_as2[s]) + adv) - m) * inv;
        const float* row = &g_h2[(size_t)s * F2];
        a0 = fmaf(al, row[lane], a0);
        if (lane < 8) a1 = fmaf(al, row[32 + lane], a1);
    }
    float v0 = a0 + b2[lane];
    float v1 = (lane < 8) ? (a1 + b2[32 + lane]) : NINF;

    float mm = fmaxf(v0, v1);
#pragma unroll
    for (int off = 16; off; off >>= 1)
        mm = fmaxf(mm, __shfl_xor_sync(0xffffffffu, mm, off));
    float s2 = expf(v0 - mm) + ((lane < 8) ? expf(v1 - mm) : 0.f);
#pragma unroll
    for (int off = 16; off; off >>= 1)
        s2 += __shfl_xor_sync(0xffffffffu, s2, off);
    const float lg = logf(s2);

    float* orow = &out[(size_t)node * F2];
    orow[lane] = v0 - mm - lg;
    if (lane < 8) orow[32 + lane] = v1 - mm - lg;
}

// ---------------- launch ----------------
extern "C" void kernel_launch(void* const* d_in, const int* in_sizes, int n_in,
                              void* d_out, int out_size) {
    const float* x   = (const float*)d_in[0];
    const void*  ei  = d_in[1];
    const float* W1  = (const float*)d_in[2];
    const float* as1 = (const float*)d_in[3];
    const float* ad1 = (const float*)d_in[4];
    const float* b1  = (const float*)d_in[5];
    const float* W2  = (const float*)d_in[6];
    const float* as2 = (const float*)d_in[7];
    const float* ad2 = (const float*)d_in[8];
    const float* b2  = (const float*)d_in[9];
    float* out = (float*)d_out;

    static int smem_set = 0;
    if (!smem_set) {
        cudaFuncSetAttribute(k_gemm1h, cudaFuncAttributeMaxDynamicSharedMemorySize, T1_TOTAL);
        smem_set = 1;
    }

    k_init<<<SCAN_BLOCKS, 256>>>((const int*)ei);                // #1
    k_split_w<<<128, 256>>>(W1);                                 // #2
    k_convert_count<<<(E_EDGES + 255) / 256, 256>>>(ei);         // #3
    dim3 gt(2, (N_NODES + 127) / 128);
    k_gemm1h<<<gt, 256, T1_TOTAL>>>(x, as1, ad1);                // #4  <- profiled
    k_bsum<<<SCAN_BLOCKS, 256>>>();                              // #5
    k_rowstart2<<<SCAN_BLOCKS, 256>>>();                         // #6
    k_scatter<<<(E_TOT + 255) / 256, 256>>>();                   // #7
    k_agg1w<<<N_NODES / 8, 256>>>(b1);                           // #8
    k_gemm2<<<(N_NODES + BM2 - 1) / BM2, 256>>>(W2, as2, ad2);   // #9
    k_agg2w<<<N_NODES / 8, 256>>>(b2, out);                      // #10
}

// round 15
// speedup vs baseline: 1.7922x; 1.1279x over previous
#include <cuda_runtime.h>
#include <cuda_bf16.h>
#include <math.h>
#include <stdint.h>

#define N_NODES 50000
#define E_EDGES 800000
#define E_TOT   (E_EDGES + N_NODES)
#define IN_DIM  512
#define F1      256
#define NH1     4
#define F2      40
#define NEG_SLOPE 0.2f
#define NINF (-__int_as_float(0x7f800000))
#define SCAN_BLOCKS 196

// ---------------- scratch ----------------
__device__ int   g_is64;
__device__ int   g_src[E_EDGES];
__device__ int   g_dst[E_EDGES];
__device__ int   g_deg[N_NODES];
__device__ int   g_bsum[SCAN_BLOCKS];
__device__ int   g_rowstart[N_NODES + 1];
__device__ int   g_cursor[N_NODES];
__device__ int   g_csr[E_TOT];
__device__ __align__(16) float g_h1[(size_t)N_NODES * F1];
__device__ __align__(16) float g_as1[N_NODES * NH1];
__device__ __align__(16) float g_ad1[N_NODES * NH1];
__device__ __align__(16) float g_hmid[(size_t)N_NODES * F1];
__device__ __align__(16) float g_h2[(size_t)N_NODES * F2];
__device__ float g_as2[N_NODES];
__device__ float g_ad2[N_NODES];
// bf16 split W1, transposed to [n][k]
__device__ __align__(16) __nv_bfloat16 g_wt1[(size_t)F1 * IN_DIM];
__device__ __align__(16) __nv_bfloat16 g_wt2[(size_t)F1 * IN_DIM];

// ---------------- helpers ----------------
__device__ __forceinline__ float lrelu(float x) { return x > 0.f ? x : NEG_SLOPE * x; }

__device__ __forceinline__ uint32_t smem_u32(const void* p) {
    uint32_t a;
    asm("{ .reg .u64 t; cvta.to.shared.u64 t, %1; cvt.u32.u64 %0, t; }" : "=r"(a) : "l"(p));
    return a;
}

#define LDSM_X4(r, a) \
    asm volatile("ldmatrix.sync.aligned.m8n8.x4.shared.b16 {%0,%1,%2,%3}, [%4];" \
        : "=r"((r)[0]), "=r"((r)[1]), "=r"((r)[2]), "=r"((r)[3]) : "r"(a))

#define MMA_BF16(c, a, b0, b1) \
    asm volatile("mma.sync.aligned.m16n8k16.row.col.f32.bf16.bf16.f32 " \
        "{%0,%1,%2,%3}, {%4,%5,%6,%7}, {%8,%9}, {%0,%1,%2,%3};" \
        : "+f"((c)[0]), "+f"((c)[1]), "+f"((c)[2]), "+f"((c)[3]) \
        : "r"((a)[0]), "r"((a)[1]), "r"((a)[2]), "r"((a)[3]), "r"(b0), "r"(b1))

#define CP_ASYNC16(dst, src) \
    asm volatile("cp.async.cg.shared.global [%0], [%1], 16;" :: "r"(dst), "l"(src) : "memory")
#define CP_COMMIT() asm volatile("cp.async.commit_group;" ::: "memory")
#define CP_WAIT0()  asm volatile("cp.async.wait_group 0;" ::: "memory")

// ---------------- init ----------------
__global__ void k_init(const int* e32) {
    int i = blockIdx.x * blockDim.x + threadIdx.x;
    if (i < N_NODES) g_deg[i] = 1;
    if (i == 0) {
        int allzero = 1;
        for (int j = 1; j < 256; j += 2) if (e32[j] != 0) allzero = 0;
        g_is64 = allzero;
    }
}

__global__ void k_convert_count(const void* eptr) {
    int i = blockIdx.x * blockDim.x + threadIdx.x;
    if (i >= E_EDGES) return;
    int s, d;
    if (g_is64) {
        const long long* e = (const long long*)eptr;
        s = (int)e[i];
        d = (int)e[E_EDGES + i];
    } else {
        const int* e = (const int*)eptr;
        s = e[i];
        d = e[E_EDGES + i];
    }
    g_src[i] = s;
    g_dst[i] = d;
    atomicAdd(&g_deg[d], 1);
}

// ---------------- W1 transpose + bf16 split (tiled) ----------------
__global__ void k_split_w(const float* __restrict__ W) {
    __shared__ float tile[32][33];
    const int t = threadIdx.x;
    const int tx = t & 31, ty = t >> 5;
    const int k0 = (blockIdx.x & 15) * 32;
    const int n0 = (blockIdx.x >> 4) * 32;
#pragma unroll
    for (int i = 0; i < 4; i++)
        tile[ty * 4 + i][tx] = W[(size_t)(k0 + ty * 4 + i) * F1 + n0 + tx];
    __syncthreads();
#pragma unroll
    for (int i = 0; i < 4; i++) {
        int n = n0 + ty * 4 + i;
        float v = tile[tx][ty * 4 + i];
        __nv_bfloat16 h = __float2bfloat16(v);
        g_wt1[(size_t)n * IN_DIM + k0 + tx] = h;
        g_wt2[(size_t)n * IN_DIM + k0 + tx] = __float2bfloat16(v - __bfloat162float(h));
    }
}

// ---------------- CSR scan ----------------
__global__ void k_bsum() {
    __shared__ int sh[256];
    const int b = blockIdx.x, t = threadIdx.x;
    const int i = b * 256 + t;
    sh[t] = (i < N_NODES) ? g_deg[i] : 0;
    __syncthreads();
#pragma unroll
    for (int off = 128; off; off >>= 1) {
        if (t < off) sh[t] += sh[t + off];
        __syncthreads();
    }
    if (t == 0) g_bsum[b] = sh[0];
}

__global__ void k_rowstart2() {
    __shared__ int sred[256];
    __shared__ int sh[256];
    const int b = blockIdx.x, t = threadIdx.x;
    sred[t] = (t < b) ? g_bsum[t] : 0;
    __syncthreads();
#pragma unroll
    for (int off = 128; off; off >>= 1) {
        if (t < off) sred[t] += sred[t + off];
        __syncthreads();
    }
    const int boff = sred[0];
    const int i = b * 256 + t;
    const int v = (i < N_NODES) ? g_deg[i] : 0;
    sh[t] = v;
    __syncthreads();
#pragma unroll
    for (int off = 1; off < 256; off <<= 1) {
        int u = (t >= off) ? sh[t - off] : 0;
        __syncthreads();
        sh[t] += u;
        __syncthreads();
    }
    const int excl = boff + sh[t] - v;
    if (i < N_NODES) {
        g_rowstart[i] = excl;
        g_cursor[i]   = excl;
        if (i == N_NODES - 1) g_rowstart[N_NODES] = excl + v;
    }
}

__global__ void k_scatter() {
    int i = blockIdx.x * blockDim.x + threadIdx.x;
    if (i >= E_TOT) return;
    int s, d;
    if (i < E_EDGES) { s = g_src[i]; d = g_dst[i]; }
    else             { s = d = i - E_EDGES; }
    int pos = atomicAdd(&g_cursor[d], 1);
    g_csr[pos] = s;
}

// ---------------- GEMM1 via HMMA, double-buffered pipeline ----------------
// CTA 128x128, 8 warps (4M x 2N), K-chunks of 32. One sync per chunk:
// B staged by cp.async, A prefetched to regs (LDG before compute, STS after).
#define STRIDE_B 112
#define BUFSZ 57344                   // 4 tiles x 14336 per buffer
#define T1_A1 0
#define T1_A2 14336
#define T1_B1 28672
#define T1_B2 43008
#define T1_SA (2 * BUFSZ)             // 114688
#define T1_SD (T1_SA + 512)
#define T1_TOTAL (T1_SD + 512)        // 115712

__global__ __launch_bounds__(256) void k_gemm1h(const float* __restrict__ x,
                                                const float* __restrict__ atts,
                                                const float* __restrict__ attd) {
    extern __shared__ __align__(16) char smem[];
    const uint32_t sb = smem_u32(smem);
    const int t = threadIdx.x;
    const int wid = t >> 5, lane = t & 31;
    const int bm = blockIdx.y * 128;
    const int bn = blockIdx.x * 128;
    const int wm = (wid & 3) * 32;
    const int wn = (wid >> 2) * 64;

    if (t < 128) {
        ((float*)(smem + T1_SA))[t] = atts[bn + t];
        ((float*)(smem + T1_SD))[t] = attd[bn + t];
    }

    // staging index precompute
    const int arow = t >> 3, ajc = (t & 7) * 4;          // A: f = t + q*256 -> here per-q recompute
    const int brow = t >> 2, bjc = (t & 3) * 8;          // B: per-q recompute

    float acc[2][8][4];
#pragma unroll
    for (int mi = 0; mi < 2; mi++)
#pragma unroll
        for (int ni = 0; ni < 8; ni++)
#pragma unroll
            for (int q = 0; q < 4; q++) acc[mi][ni][q] = 0.f;

    const int lr = lane & 7;
    const int aRow = lr + 8 * ((lane >> 3) & 1);
    const int aKk  = 8 * (lane >> 4);
    const int bRow = lr + 8 * (lane >> 4);
    const int bKk  = 8 * ((lane >> 3) & 1);

    // ---- helper lambdas (inlined) ----
    auto issueB = [&](int k0, uint32_t base) {
#pragma unroll
        for (int q = 0; q < 2; q++) {
            int f = t + q * 256;
            int row = f >> 2, jc = (f & 3) * 8;
            const __nv_bfloat16* s1 = g_wt1 + (size_t)(bn + row) * IN_DIM + k0 + jc;
            const __nv_bfloat16* s2 = g_wt2 + (size_t)(bn + row) * IN_DIM + k0 + jc;
            CP_ASYNC16(base + T1_B1 + row * STRIDE_B + jc * 2, s1);
            CP_ASYNC16(base + T1_B2 + row * STRIDE_B + jc * 2, s2);
        }
        CP_COMMIT();
    };
    auto loadA = [&](int k0, float4* pa) {
#pragma unroll
        for (int q = 0; q < 4; q++) {
            int f = t + q * 256;
            int row = f >> 3, jc = (f & 7) * 4;
            pa[q] = make_float4(0.f, 0.f, 0.f, 0.f);
            int gr = bm + row;
            if (gr < N_NODES) pa[q] = *(const float4*)&x[(size_t)gr * IN_DIM + k0 + jc];
        }
    };
    auto storeA = [&](const float4* pa, uint32_t baseOff) {
        char* bp = smem + baseOff;
#pragma unroll
        for (int q = 0; q < 4; q++) {
            int f = t + q * 256;
            int row = f >> 3, jc = (f & 7) * 4;
            float4 v = pa[q];
            __nv_bfloat16 h0 = __float2bfloat16(v.x), h1 = __float2bfloat16(v.y);
            __nv_bfloat16 h2 = __float2bfloat16(v.z), h3 = __float2bfloat16(v.w);
            __nv_bfloat16 l0 = __float2bfloat16(v.x - __bfloat162float(h0));
            __nv_bfloat16 l1 = __float2bfloat16(v.y - __bfloat162float(h1));
            __nv_bfloat16 l2 = __float2bfloat16(v.z - __bfloat162float(h2));
            __nv_bfloat16 l3 = __float2bfloat16(v.w - __bfloat162float(h3));
            uint2 hi, lo;
            hi.x = (uint32_t)__bfloat16_as_ushort(h0) | ((uint32_t)__bfloat16_as_ushort(h1) << 16);
            hi.y = (uint32_t)__bfloat16_as_ushort(h2) | ((uint32_t)__bfloat16_as_ushort(h3) << 16);
            lo.x = (uint32_t)__bfloat16_as_ushort(l0) | ((uint32_t)__bfloat16_as_ushort(l1) << 16);
            lo.y = (uint32_t)__bfloat16_as_ushort(l2) | ((uint32_t)__bfloat16_as_ushort(l3) << 16);
            *(uint2*)(bp + T1_A1 + row * STRIDE_B + jc * 2) = hi;
            *(uint2*)(bp + T1_A2 + row * STRIDE_B + jc * 2) = lo;
        }
    };

    // prologue: stage chunk 0 into buffer 0
    {
        float4 pa0[4];
        loadA(0, pa0);
        issueB(0, sb + 0);
        storeA(pa0, 0);
        CP_WAIT0();
    }
    __syncthreads();

    uint32_t buf = 0;
    float4 pa[4];
    for (int c = 0; c < IN_DIM / 32; c++) {
        const int k0 = c * 32;
        const bool has_next = (c + 1) < IN_DIM / 32;
        const uint32_t nbuf = buf ^ BUFSZ;
        if (has_next) {
            loadA(k0 + 32, pa);           // LDG in flight during compute
            issueB(k0 + 32, sb + nbuf);   // cp.async in flight during compute
        }

        const uint32_t sA1 = sb + buf + T1_A1;
        const uint32_t sA2 = sb + buf + T1_A2;
        const uint32_t sB1 = sb + buf + T1_B1;
        const uint32_t sB2 = sb + buf + T1_B2;
#pragma unroll
        for (int ks = 0; ks < 32; ks += 16) {
            uint32_t a1f[2][4], a2f[2][4];
#pragma unroll
            for (int mi = 0; mi < 2; mi++) {
                uint32_t off = (uint32_t)((wm + mi * 16 + aRow) * STRIDE_B + (ks + aKk) * 2);
                LDSM_X4(a1f[mi], sA1 + off);
                LDSM_X4(a2f[mi], sA2 + off);
            }
#pragma unroll
            for (int njp = 0; njp < 4; njp++) {
                uint32_t b1f[4], b2f[4];
                uint32_t off = (uint32_t)((wn + njp * 16 + bRow) * STRIDE_B + (ks + bKk) * 2);
                LDSM_X4(b1f, sB1 + off);
                LDSM_X4(b2f, sB2 + off);
#pragma unroll
                for (int h = 0; h < 2; h++) {
                    int ni = njp * 2 + h;
#pragma unroll
                    for (int mi = 0; mi < 2; mi++) {
                        MMA_BF16(acc[mi][ni], a1f[mi], b1f[2 * h], b1f[2 * h + 1]);
                        MMA_BF16(acc[mi][ni], a1f[mi], b2f[2 * h], b2f[2 * h + 1]);
                        MMA_BF16(acc[mi][ni], a2f[mi], b1f[2 * h], b1f[2 * h + 1]);
                    }
                }
            }
        }

        if (has_next) {
            storeA(pa, nbuf);   // convert + STS after compute
            CP_WAIT0();
        }
        __syncthreads();
        buf = nbuf;
    }

    // epilogue: store h1 + direct attention-dot stores (warp owns one head)
    const int group = lane >> 2, qt = lane & 3;
    const float* sa = (const float*)(smem + T1_SA);
    const float* sd = (const float*)(smem + T1_SD);
    const int head = (bn >> 6) + (wn >> 6);
#pragma unroll
    for (int mi = 0; mi < 2; mi++) {
#pragma unroll
        for (int hr = 0; hr < 2; hr++) {
            int r = bm + wm + mi * 16 + group + hr * 8;
            float ps = 0.f, pd = 0.f;
            if (r < N_NODES) {
#pragma unroll
                for (int ni = 0; ni < 8; ni++) {
                    float v0 = acc[mi][ni][hr * 2], v1 = acc[mi][ni][hr * 2 + 1];
                    int cl = wn + ni * 8 + qt * 2;
                    *(float2*)&g_h1[(size_t)r * F1 + bn + cl] = make_float2(v0, v1);
                    ps = fmaf(v0, sa[cl], ps); ps = fmaf(v1, sa[cl + 1], ps);
                    pd = fmaf(v0, sd[cl], pd); pd = fmaf(v1, sd[cl + 1], pd);
                }
            }
            ps += __shfl_xor_sync(0xffffffffu, ps, 1);
            ps += __shfl_xor_sync(0xffffffffu, ps, 2);
            pd += __shfl_xor_sync(0xffffffffu, pd, 1);
            pd += __shfl_xor_sync(0xffffffffu, pd, 2);
            if (qt == 0 && r < N_NODES) {
                g_as1[r * 4 + head] = ps;
                g_ad1[r * 4 + head] = pd;
            }
        }
    }
}

// ---------------- layer-1 aggregation: WARP per node ----------------
__global__ __launch_bounds__(256) void k_agg1w(const float* __restrict__ b1) {
    const int node = blockIdx.x * 8 + (threadIdx.x >> 5);
    const int lane = threadIdx.x & 31;
    const int start = g_rowstart[node];
    const int cnt = g_rowstart[node + 1] - start;

    float4 adv = *(const float4*)&g_ad1[node * 4];

    float m0 = NINF, m1 = NINF, m2 = NINF, m3 = NINF;
    for (int e = lane; e < cnt; e += 32) {
        int s = g_csr[start + e];
        float4 av = *(const float4*)&g_as1[s * 4];
        m0 = fmaxf(m0, lrelu(av.x + adv.x));
        m1 = fmaxf(m1, lrelu(av.y + adv.y));
        m2 = fmaxf(m2, lrelu(av.z + adv.z));
        m3 = fmaxf(m3, lrelu(av.w + adv.w));
    }
#pragma unroll
    for (int off = 16; off; off >>= 1) {
        m0 = fmaxf(m0, __shfl_xor_sync(0xffffffffu, m0, off));
        m1 = fmaxf(m1, __shfl_xor_sync(0xffffffffu, m1, off));
        m2 = fmaxf(m2, __shfl_xor_sync(0xffffffffu, m2, off));
        m3 = fmaxf(m3, __shfl_xor_sync(0xffffffffu, m3, off));
    }

    float s0 = 0.f, s1 = 0.f, s2 = 0.f, s3 = 0.f;
    for (int e = lane; e < cnt; e += 32) {
        int s = g_csr[start + e];
        float4 av = *(const float4*)&g_as1[s * 4];
        s0 += expf(lrelu(av.x + adv.x) - m0);
        s1 += expf(lrelu(av.y + adv.y) - m1);
        s2 += expf(lrelu(av.z + adv.z) - m2);
        s3 += expf(lrelu(av.w + adv.w) - m3);
    }
#pragma unroll
    for (int off = 16; off; off >>= 1) {
        s0 += __shfl_xor_sync(0xffffffffu, s0, off);
        s1 += __shfl_xor_sync(0xffffffffu, s1, off);
        s2 += __shfl_xor_sync(0xffffffffu, s2, off);
        s3 += __shfl_xor_sync(0xffffffffu, s3, off);
    }

    const int hh = lane >> 3;
    float advh = (hh == 0) ? adv.x : (hh == 1) ? adv.y : (hh == 2) ? adv.z : adv.w;
    float mh   = (hh == 0) ? m0    : (hh == 1) ? m1    : (hh == 2) ? m2    : m3;
    float sumh = (hh == 0) ? s0    : (hh == 1) ? s1    : (hh == 2) ? s2    : s3;
    const float invh = 1.f / (sumh + 1e-16f);

    float4 a0 = make_float4(0.f, 0.f, 0.f, 0.f);
    float4 a1 = make_float4(0.f, 0.f, 0.f, 0.f);
    const int coff = lane * 8;
    for (int e = 0; e < cnt; e++) {
        int s = g_csr[start + e];
        float av = __ldg(&g_as1[s * 4 + hh]);
        float al = expf(lrelu(av + advh) - mh) * invh;
        const float* row = &g_h1[(size_t)s * F1 + coff];
        float4 v0 = *(const float4*)row;
        float4 v1 = *(const float4*)(row + 4);
        a0.x = fmaf(al, v0.x, a0.x); a0.y = fmaf(al, v0.y, a0.y);
        a0.z = fmaf(al, v0.z, a0.z); a0.w = fmaf(al, v0.w, a0.w);
        a1.x = fmaf(al, v1.x, a1.x); a1.y = fmaf(al, v1.y, a1.y);
        a1.z = fmaf(al, v1.z, a1.z); a1.w = fmaf(al, v1.w, a1.w);
    }

    float4 bb0 = *(const float4*)&b1[coff];
    float4 bb1 = *(const float4*)&b1[coff + 4];
    float r0 = a0.x + bb0.x, r1 = a0.y + bb0.y, r2 = a0.z + bb0.z, r3 = a0.w + bb0.w;
    float r4 = a1.x + bb1.x, r5 = a1.y + bb1.y, r6 = a1.z + bb1.z, r7 = a1.w + bb1.w;
    r0 = r0 > 0.f ? r0 : expm1f(r0); r1 = r1 > 0.f ? r1 : expm1f(r1);
    r2 = r2 > 0.f ? r2 : expm1f(r2); r3 = r3 > 0.f ? r3 : expm1f(r3);
    r4 = r4 > 0.f ? r4 : expm1f(r4); r5 = r5 > 0.f ? r5 : expm1f(r5);
    r6 = r6 > 0.f ? r6 : expm1f(r6); r7 = r7 > 0.f ? r7 : expm1f(r7);
    float* orow = &g_hmid[(size_t)node * F1 + coff];
    *(float4*)orow       = make_float4(r0, r1, r2, r3);
    *(float4*)(orow + 4) = make_float4(r4, r5, r6, r7);
}

// ---------------- GEMM2 + fused attention dots ----------------
#define BM2 128
#define BK2 32
#define A2PAD 132
__global__ __launch_bounds__(256) void k_gemm2(const float* __restrict__ W2,
                                               const float* __restrict__ atts,
                                               const float* __restrict__ attd) {
    __shared__ __align__(16) float As2t[BK2][A2PAD];
    __shared__ __align__(16) float Ws[BK2][F2];
    const int bm = blockIdx.x * BM2;
    const int t = threadIdx.x;
    const int tx = t & 7;
    const int ty = t >> 3;
    float acc[4][5];
#pragma unroll
    for (int i = 0; i < 4; i++)
#pragma unroll
        for (int j = 0; j < 5; j++) acc[i][j] = 0.f;

    for (int k0 = 0; k0 < F1; k0 += BK2) {
#pragma unroll
        for (int r = 0; r < 4; r++) {
            int f = t + r * 256;
            int row = f >> 3;
            int cv = (f & 7) * 4;
            float4 v = make_float4(0.f, 0.f, 0.f, 0.f);
            int gr = bm + row;
            if (gr < N_NODES) v = *(const float4*)&g_hmid[(size_t)gr * F1 + k0 + cv];
            As2t[cv + 0][row] = v.x;
            As2t[cv + 1][row] = v.y;
            As2t[cv + 2][row] = v.z;
            As2t[cv + 3][row] = v.w;
        }
        for (int idx = t; idx < BK2 * F2; idx += 256) {
            int r = idx / F2, c = idx % F2;
            Ws[r][c] = W2[(size_t)(k0 + r) * F2 + c];
        }
        __syncthreads();
#pragma unroll
        for (int kk = 0; kk < BK2; kk++) {
            float4 a4 = *(const float4*)&As2t[kk][ty * 4];
            float a[4] = {a4.x, a4.y, a4.z, a4.w};
            float b[5];
#pragma unroll
            for (int j = 0; j < 5; j++) b[j] = Ws[kk][tx * 5 + j];
#pragma unroll
            for (int i = 0; i < 4; i++)
#pragma unroll
                for (int j = 0; j < 5; j++) acc[i][j] = fmaf(a[i], b[j], acc[i][j]);
        }
        __syncthreads();
    }

    float avS[5], avD[5];
#pragma unroll
    for (int j = 0; j < 5; j++) { avS[j] = atts[tx * 5 + j]; avD[j] = attd[tx * 5 + j]; }
#pragma unroll
    for (int i = 0; i < 4; i++) {
        int gr = bm + ty * 4 + i;
        if (gr < N_NODES)
#pragma unroll
            for (int j = 0; j < 5; j++)
                g_h2[(size_t)gr * F2 + tx * 5 + j] = acc[i][j];
        float ps = 0.f, pd = 0.f;
#pragma unroll
        for (int j = 0; j < 5; j++) {
            ps = fmaf(acc[i][j], avS[j], ps);
            pd = fmaf(acc[i][j], avD[j], pd);
        }
#pragma unroll
        for (int off = 4; off; off >>= 1) {
            ps += __shfl_down_sync(0xffffffffu, ps, off, 8);
            pd += __shfl_down_sync(0xffffffffu, pd, off, 8);
        }
        if (tx == 0 && gr < N_NODES) { g_as2[gr] = ps; g_ad2[gr] = pd; }
    }
}

// ---------------- layer-2 aggregation + log_softmax: WARP per node ----------------
__global__ __launch_bounds__(256) void k_agg2w(const float* __restrict__ b2,
                                               float* __restrict__ out) {
    const int node = blockIdx.x * 8 + (threadIdx.x >> 5);
    const int lane = threadIdx.x & 31;
    const int start = g_rowstart[node];
    const int cnt = g_rowstart[node + 1] - start;
    const float adv = g_ad2[node];

    float m = NINF;
    for (int e = lane; e < cnt; e += 32)
        m = fmaxf(m, lrelu(g_as2[g_csr[start + e]] + adv));
#pragma unroll
    for (int off = 16; off; off >>= 1)
        m = fmaxf(m, __shfl_xor_sync(0xffffffffu, m, off));

    float se = 0.f;
    for (int e = lane; e < cnt; e += 32)
        se += expf(lrelu(g_as2[g_csr[start + e]] + adv) - m);
#pragma unroll
    for (int off = 16; off; off >>= 1)
        se += __shfl_xor_sync(0xffffffffu, se, off);
    const float inv = 1.f / (se + 1e-16f);

    float a0 = 0.f, a1 = 0.f;
    for (int e = 0; e < cnt; e++) {
        int s = g_csr[start + e];
        float al = expf(lrelu(__ldg(&g_as2[s]) + adv) - m) * inv;
        const float* row = &g_h2[(size_t)s * F2];
        a0 = fmaf(al, row[lane], a0);
        if (lane < 8) a1 = fmaf(al, row[32 + lane], a1);
    }
    float v0 = a0 + b2[lane];
    float v1 = (lane < 8) ? (a1 + b2[32 + lane]) : NINF;

    float mm = fmaxf(v0, v1);
#pragma unroll
    for (int off = 16; off; off >>= 1)
        mm = fmaxf(mm, __shfl_xor_sync(0xffffffffu, mm, off));
    float s2 = expf(v0 - mm) + ((lane < 8) ? expf(v1 - mm) : 0.f);
#pragma unroll
    for (int off = 16; off; off >>= 1)
        s2 += __shfl_xor_sync(0xffffffffu, s2, off);
    const float lg = logf(s2);

    float* orow = &out[(size_t)node * F2];
    orow[lane] = v0 - mm - lg;
    if (lane < 8) orow[32 + lane] = v1 - mm - lg;
}

// ---------------- launch ----------------
extern "C" void kernel_launch(void* const* d_in, const int* in_sizes, int n_in,
                              void* d_out, int out_size) {
    const float* x   = (const float*)d_in[0];
    const void*  ei  = d_in[1];
    const float* W1  = (const float*)d_in[2];
    const float* as1 = (const float*)d_in[3];
    const float* ad1 = (const float*)d_in[4];
    const float* b1  = (const float*)d_in[5];
    const float* W2  = (const float*)d_in[6];
    const float* as2 = (const float*)d_in[7];
    const float* ad2 = (const float*)d_in[8];
    const float* b2  = (const float*)d_in[9];
    float* out = (float*)d_out;

    static int smem_set = 0;
    if (!smem_set) {
        cudaFuncSetAttribute(k_gemm1h, cudaFuncAttributeMaxDynamicSharedMemorySize, T1_TOTAL);
        smem_set = 1;
    }

    k_init<<<SCAN_BLOCKS, 256>>>((const int*)ei);                // #1
    k_split_w<<<128, 256>>>(W1);                                 // #2
    k_convert_count<<<(E_EDGES + 255) / 256, 256>>>(ei);         // #3
    dim3 gt(2, (N_NODES + 127) / 128);
    k_gemm1h<<<gt, 256, T1_TOTAL>>>(x, as1, ad1);                // #4  <- profiled
    k_bsum<<<SCAN_BLOCKS, 256>>>();                              // #5
    k_rowstart2<<<SCAN_BLOCKS, 256>>>();                         // #6
    k_scatter<<<(E_TOT + 255) / 256, 256>>>();                   // #7
    k_agg1w<<<N_NODES / 8, 256>>>(b1);                           // #8
    k_gemm2<<<(N_NODES + BM2 - 1) / BM2, 256>>>(W2, as2, ad2);   // #9
    k_agg2w<<<N_NODES / 8, 256>>>(b2, out);                      // #10
}

// round 16
// speedup vs baseline: 1.9066x; 1.0638x over previous
#include <cuda_runtime.h>
#include <cuda_bf16.h>
#include <math.h>
#include <stdint.h>

#define N_NODES 50000
#define E_EDGES 800000
#define E_TOT   (E_EDGES + N_NODES)
#define IN_DIM  512
#define F1      256
#define NH1     4
#define F2      40
#define NEG_SLOPE 0.2f
#define NINF (-__int_as_float(0x7f800000))
#define SCAN_BLOCKS 196

// ---------------- scratch ----------------
__device__ int   g_is64;
__device__ int   g_src[E_EDGES];
__device__ int   g_dst[E_EDGES];
__device__ int   g_deg[N_NODES];
__device__ int   g_bsum[SCAN_BLOCKS];
__device__ int   g_rowstart[N_NODES + 1];
__device__ int   g_cursor[N_NODES];
__device__ int   g_csr[E_TOT];
__device__ __align__(16) float g_h1[(size_t)N_NODES * F1];
__device__ __align__(16) float g_as1[N_NODES * NH1];
__device__ __align__(16) float g_ad1[N_NODES * NH1];
__device__ __align__(16) float g_hmid[(size_t)N_NODES * F1];
__device__ __align__(16) float g_h2[(size_t)N_NODES * F2];
__device__ float g_as2[N_NODES];
__device__ float g_ad2[N_NODES];
// bf16 split W1, transposed to [n][k]
__device__ __align__(16) __nv_bfloat16 g_wt1[(size_t)F1 * IN_DIM];
__device__ __align__(16) __nv_bfloat16 g_wt2[(size_t)F1 * IN_DIM];

// ---------------- helpers ----------------
__device__ __forceinline__ float lrelu(float x) { return x > 0.f ? x : NEG_SLOPE * x; }

__device__ __forceinline__ uint32_t smem_u32(const void* p) {
    uint32_t a;
    asm("{ .reg .u64 t; cvta.to.shared.u64 t, %1; cvt.u32.u64 %0, t; }" : "=r"(a) : "l"(p));
    return a;
}

#define LDSM_X4(r, a) \
    asm volatile("ldmatrix.sync.aligned.m8n8.x4.shared.b16 {%0,%1,%2,%3}, [%4];" \
        : "=r"((r)[0]), "=r"((r)[1]), "=r"((r)[2]), "=r"((r)[3]) : "r"(a))

#define MMA_BF16(c, a, b0, b1) \
    asm volatile("mma.sync.aligned.m16n8k16.row.col.f32.bf16.bf16.f32 " \
        "{%0,%1,%2,%3}, {%4,%5,%6,%7}, {%8,%9}, {%0,%1,%2,%3};" \
        : "+f"((c)[0]), "+f"((c)[1]), "+f"((c)[2]), "+f"((c)[3]) \
        : "r"((a)[0]), "r"((a)[1]), "r"((a)[2]), "r"((a)[3]), "r"(b0), "r"(b1))

#define CP_ASYNC16(dst, src) \
    asm volatile("cp.async.cg.shared.global [%0], [%1], 16;" :: "r"(dst), "l"(src) : "memory")
#define CP_COMMIT() asm volatile("cp.async.commit_group;" ::: "memory")
#define CP_WAIT0()  asm volatile("cp.async.wait_group 0;" ::: "memory")

// ---------------- init ----------------
__global__ void k_init(const int* e32) {
    int i = blockIdx.x * blockDim.x + threadIdx.x;
    if (i < N_NODES) g_deg[i] = 1;
    if (i == 0) {
        int allzero = 1;
        for (int j = 1; j < 256; j += 2) if (e32[j] != 0) allzero = 0;
        g_is64 = allzero;
    }
}

__global__ void k_convert_count(const void* eptr) {
    int i = blockIdx.x * blockDim.x + threadIdx.x;
    if (i >= E_EDGES) return;
    int s, d;
    if (g_is64) {
        const long long* e = (const long long*)eptr;
        s = (int)e[i];
        d = (int)e[E_EDGES + i];
    } else {
        const int* e = (const int*)eptr;
        s = e[i];
        d = e[E_EDGES + i];
    }
    g_src[i] = s;
    g_dst[i] = d;
    atomicAdd(&g_deg[d], 1);
}

// ---------------- W1 transpose + bf16 split (tiled) ----------------
__global__ void k_split_w(const float* __restrict__ W) {
    __shared__ float tile[32][33];
    const int t = threadIdx.x;
    const int tx = t & 31, ty = t >> 5;
    const int k0 = (blockIdx.x & 15) * 32;
    const int n0 = (blockIdx.x >> 4) * 32;
#pragma unroll
    for (int i = 0; i < 4; i++)
        tile[ty * 4 + i][tx] = W[(size_t)(k0 + ty * 4 + i) * F1 + n0 + tx];
    __syncthreads();
#pragma unroll
    for (int i = 0; i < 4; i++) {
        int n = n0 + ty * 4 + i;
        float v = tile[tx][ty * 4 + i];
        __nv_bfloat16 h = __float2bfloat16(v);
        g_wt1[(size_t)n * IN_DIM + k0 + tx] = h;
        g_wt2[(size_t)n * IN_DIM + k0 + tx] = __float2bfloat16(v - __bfloat162float(h));
    }
}

// ---------------- CSR scan ----------------
__global__ void k_bsum() {
    __shared__ int sh[256];
    const int b = blockIdx.x, t = threadIdx.x;
    const int i = b * 256 + t;
    sh[t] = (i < N_NODES) ? g_deg[i] : 0;
    __syncthreads();
#pragma unroll
    for (int off = 128; off; off >>= 1) {
        if (t < off) sh[t] += sh[t + off];
        __syncthreads();
    }
    if (t == 0) g_bsum[b] = sh[0];
}

__global__ void k_rowstart2() {
    __shared__ int sred[256];
    __shared__ int sh[256];
    const int b = blockIdx.x, t = threadIdx.x;
    sred[t] = (t < b) ? g_bsum[t] : 0;
    __syncthreads();
#pragma unroll
    for (int off = 128; off; off >>= 1) {
        if (t < off) sred[t] += sred[t + off];
        __syncthreads();
    }
    const int boff = sred[0];
    const int i = b * 256 + t;
    const int v = (i < N_NODES) ? g_deg[i] : 0;
    sh[t] = v;
    __syncthreads();
#pragma unroll
    for (int off = 1; off < 256; off <<= 1) {
        int u = (t >= off) ? sh[t - off] : 0;
        __syncthreads();
        sh[t] += u;
        __syncthreads();
    }
    const int excl = boff + sh[t] - v;
    if (i < N_NODES) {
        g_rowstart[i] = excl;
        g_cursor[i]   = excl;
        if (i == N_NODES - 1) g_rowstart[N_NODES] = excl + v;
    }
}

__global__ void k_scatter() {
    int i = blockIdx.x * blockDim.x + threadIdx.x;
    if (i >= E_TOT) return;
    int s, d;
    if (i < E_EDGES) { s = g_src[i]; d = g_dst[i]; }
    else             { s = d = i - E_EDGES; }
    int pos = atomicAdd(&g_cursor[d], 1);
    g_csr[pos] = s;
}

// ---------------- GEMM1 via HMMA, double-buffered, K-chunk 16, 2 CTAs/SM ----
// smem row stride 48B (16B aligned, conflict-free ldmatrix).
// Buffers: 4 tiles x 6KB = 24KB each, x2 = 48KB + 1KB attn = ~49KB/CTA.
#define KCH 16
#define RSTRIDE 48
#define TILE_SZ (128 * RSTRIDE)       // 6144
#define T1_A1 0
#define T1_A2 TILE_SZ
#define T1_B1 (2 * TILE_SZ)
#define T1_B2 (3 * TILE_SZ)
#define BUFSZ (4 * TILE_SZ)           // 24576
#define T1_SA (2 * BUFSZ)             // 49152
#define T1_SD (T1_SA + 512)
#define T1_TOTAL (T1_SD + 512)        // 50176

__global__ __launch_bounds__(256, 2) void k_gemm1h(const float* __restrict__ x,
                                                   const float* __restrict__ atts,
                                                   const float* __restrict__ attd) {
    extern __shared__ __align__(16) char smem[];
    const uint32_t sb = smem_u32(smem);
    const int t = threadIdx.x;
    const int wid = t >> 5, lane = t & 31;
    const int bm = blockIdx.y * 128;
    const int bn = blockIdx.x * 128;
    const int wm = (wid & 3) * 32;
    const int wn = (wid >> 2) * 64;

    if (t < 128) {
        ((float*)(smem + T1_SA))[t] = atts[bn + t];
        ((float*)(smem + T1_SD))[t] = attd[bn + t];
    }

    float acc[2][8][4];
#pragma unroll
    for (int mi = 0; mi < 2; mi++)
#pragma unroll
        for (int ni = 0; ni < 8; ni++)
#pragma unroll
            for (int q = 0; q < 4; q++) acc[mi][ni][q] = 0.f;

    const int lr = lane & 7;
    const int aRow = lr + 8 * ((lane >> 3) & 1);
    const int aKk  = 8 * (lane >> 4);
    const int bRow = lr + 8 * (lane >> 4);
    const int bKk  = 8 * ((lane >> 3) & 1);

    // B staging via cp.async: 2 tiles x 128 rows x 32B = 512 x16B; thread does 2.
    auto issueB = [&](int k0, uint32_t base) {
        {
            int row = t >> 1, half = t & 1;
            const __nv_bfloat16* s1 = g_wt1 + (size_t)(bn + row) * IN_DIM + k0 + half * 8;
            CP_ASYNC16(base + T1_B1 + row * RSTRIDE + half * 16, s1);
            const __nv_bfloat16* s2 = g_wt2 + (size_t)(bn + row) * IN_DIM + k0 + half * 8;
            CP_ASYNC16(base + T1_B2 + row * RSTRIDE + half * 16, s2);
        }
        CP_COMMIT();
    };
    // A: 128 rows x 16 k fp32 = 512 float4; thread does 2.
    auto loadA = [&](int k0, float4* pa) {
#pragma unroll
        for (int q = 0; q < 2; q++) {
            int f = t + q * 256;
            int row = f >> 2, jc = (f & 3) * 4;
            pa[q] = make_float4(0.f, 0.f, 0.f, 0.f);
            int gr = bm + row;
            if (gr < N_NODES) pa[q] = *(const float4*)&x[(size_t)gr * IN_DIM + k0 + jc];
        }
    };
    auto storeA = [&](const float4* pa, uint32_t baseOff) {
        char* bp = smem + baseOff;
#pragma unroll
        for (int q = 0; q < 2; q++) {
            int f = t + q * 256;
            int row = f >> 2, jc = (f & 3) * 4;
            float4 v = pa[q];
            __nv_bfloat16 h0 = __float2bfloat16(v.x), h1 = __float2bfloat16(v.y);
            __nv_bfloat16 h2 = __float2bfloat16(v.z), h3 = __float2bfloat16(v.w);
            __nv_bfloat16 l0 = __float2bfloat16(v.x - __bfloat162float(h0));
            __nv_bfloat16 l1 = __float2bfloat16(v.y - __bfloat162float(h1));
            __nv_bfloat16 l2 = __float2bfloat16(v.z - __bfloat162float(h2));
            __nv_bfloat16 l3 = __float2bfloat16(v.w - __bfloat162float(h3));
            uint2 hi, lo;
            hi.x = (uint32_t)__bfloat16_as_ushort(h0) | ((uint32_t)__bfloat16_as_ushort(h1) << 16);
            hi.y = (uint32_t)__bfloat16_as_ushort(h2) | ((uint32_t)__bfloat16_as_ushort(h3) << 16);
            lo.x = (uint32_t)__bfloat16_as_ushort(l0) | ((uint32_t)__bfloat16_as_ushort(l1) << 16);
            lo.y = (uint32_t)__bfloat16_as_ushort(l2) | ((uint32_t)__bfloat16_as_ushort(l3) << 16);
            *(uint2*)(bp + T1_A1 + row * RSTRIDE + jc * 2) = hi;
            *(uint2*)(bp + T1_A2 + row * RSTRIDE + jc * 2) = lo;
        }
    };

    // prologue
    {
        float4 pa0[2];
        loadA(0, pa0);
        issueB(0, sb + 0);
        storeA(pa0, 0);
        CP_WAIT0();
    }
    __syncthreads();

    uint32_t buf = 0;
    float4 pa[2];
    for (int c = 0; c < IN_DIM / KCH; c++) {
        const int k0 = c * KCH;
        const bool has_next = (c + 1) < IN_DIM / KCH;
        const uint32_t nbuf = buf ^ BUFSZ;
        if (has_next) {
            loadA(k0 + KCH, pa);
            issueB(k0 + KCH, sb + nbuf);
        }

        const uint32_t sA1 = sb + buf + T1_A1;
        const uint32_t sA2 = sb + buf + T1_A2;
        const uint32_t sB1 = sb + buf + T1_B1;
        const uint32_t sB2 = sb + buf + T1_B2;
        {
            uint32_t a1f[2][4], a2f[2][4];
#pragma unroll
            for (int mi = 0; mi < 2; mi++) {
                uint32_t off = (uint32_t)((wm + mi * 16 + aRow) * RSTRIDE + aKk * 2);
                LDSM_X4(a1f[mi], sA1 + off);
                LDSM_X4(a2f[mi], sA2 + off);
            }
#pragma unroll
            for (int njp = 0; njp < 4; njp++) {
                uint32_t b1f[4], b2f[4];
                uint32_t off = (uint32_t)((wn + njp * 16 + bRow) * RSTRIDE + bKk * 2);
                LDSM_X4(b1f, sB1 + off);
                LDSM_X4(b2f, sB2 + off);
#pragma unroll
                for (int h = 0; h < 2; h++) {
                    int ni = njp * 2 + h;
#pragma unroll
                    for (int mi = 0; mi < 2; mi++) {
                        MMA_BF16(acc[mi][ni], a1f[mi], b1f[2 * h], b1f[2 * h + 1]);
                        MMA_BF16(acc[mi][ni], a1f[mi], b2f[2 * h], b2f[2 * h + 1]);
                        MMA_BF16(acc[mi][ni], a2f[mi], b1f[2 * h], b1f[2 * h + 1]);
                    }
                }
            }
        }

        if (has_next) {
            storeA(pa, nbuf);
            CP_WAIT0();
        }
        __syncthreads();
        buf = nbuf;
    }

    // epilogue: store h1 + direct attention-dot stores (warp owns one head)
    const int group = lane >> 2, qt = lane & 3;
    const float* sa = (const float*)(smem + T1_SA);
    const float* sd = (const float*)(smem + T1_SD);
    const int head = (bn >> 6) + (wn >> 6);
#pragma unroll
    for (int mi = 0; mi < 2; mi++) {
#pragma unroll
        for (int hr = 0; hr < 2; hr++) {
            int r = bm + wm + mi * 16 + group + hr * 8;
            float ps = 0.f, pd = 0.f;
            if (r < N_NODES) {
#pragma unroll
                for (int ni = 0; ni < 8; ni++) {
                    float v0 = acc[mi][ni][hr * 2], v1 = acc[mi][ni][hr * 2 + 1];
                    int cl = wn + ni * 8 + qt * 2;
                    *(float2*)&g_h1[(size_t)r * F1 + bn + cl] = make_float2(v0, v1);
                    ps = fmaf(v0, sa[cl], ps); ps = fmaf(v1, sa[cl + 1], ps);
                    pd = fmaf(v0, sd[cl], pd); pd = fmaf(v1, sd[cl + 1], pd);
                }
            }
            ps += __shfl_xor_sync(0xffffffffu, ps, 1);
            ps += __shfl_xor_sync(0xffffffffu, ps, 2);
            pd += __shfl_xor_sync(0xffffffffu, pd, 1);
            pd += __shfl_xor_sync(0xffffffffu, pd, 2);
            if (qt == 0 && r < N_NODES) {
                g_as1[r * 4 + head] = ps;
                g_ad1[r * 4 + head] = pd;
            }
        }
    }
}

// ---------------- layer-1 aggregation: WARP per node ----------------
__global__ __launch_bounds__(256) void k_agg1w(const float* __restrict__ b1) {
    const int node = blockIdx.x * 8 + (threadIdx.x >> 5);
    const int lane = threadIdx.x & 31;
    const int start = g_rowstart[node];
    const int cnt = g_rowstart[node + 1] - start;

    float4 adv = *(const float4*)&g_ad1[node * 4];

    float m0 = NINF, m1 = NINF, m2 = NINF, m3 = NINF;
    for (int e = lane; e < cnt; e += 32) {
        int s = g_csr[start + e];
        float4 av = *(const float4*)&g_as1[s * 4];
        m0 = fmaxf(m0, lrelu(av.x + adv.x));
        m1 = fmaxf(m1, lrelu(av.y + adv.y));
        m2 = fmaxf(m2, lrelu(av.z + adv.z));
        m3 = fmaxf(m3, lrelu(av.w + adv.w));
    }
#pragma unroll
    for (int off = 16; off; off >>= 1) {
        m0 = fmaxf(m0, __shfl_xor_sync(0xffffffffu, m0, off));
        m1 = fmaxf(m1, __shfl_xor_sync(0xffffffffu, m1, off));
        m2 = fmaxf(m2, __shfl_xor_sync(0xffffffffu, m2, off));
        m3 = fmaxf(m3, __shfl_xor_sync(0xffffffffu, m3, off));
    }

    float s0 = 0.f, s1 = 0.f, s2 = 0.f, s3 = 0.f;
    for (int e = lane; e < cnt; e += 32) {
        int s = g_csr[start + e];
        float4 av = *(const float4*)&g_as1[s * 4];
        s0 += expf(lrelu(av.x + adv.x) - m0);
        s1 += expf(lrelu(av.y + adv.y) - m1);
        s2 += expf(lrelu(av.z + adv.z) - m2);
        s3 += expf(lrelu(av.w + adv.w) - m3);
    }
#pragma unroll
    for (int off = 16; off; off >>= 1) {
        s0 += __shfl_xor_sync(0xffffffffu, s0, off);
        s1 += __shfl_xor_sync(0xffffffffu, s1, off);
        s2 += __shfl_xor_sync(0xffffffffu, s2, off);
        s3 += __shfl_xor_sync(0xffffffffu, s3, off);
    }

    const int hh = lane >> 3;
    float advh = (hh == 0) ? adv.x : (hh == 1) ? adv.y : (hh == 2) ? adv.z : adv.w;
    float mh   = (hh == 0) ? m0    : (hh == 1) ? m1    : (hh == 2) ? m2    : m3;
    float sumh = (hh == 0) ? s0    : (hh == 1) ? s1    : (hh == 2) ? s2    : s3;
    const float invh = 1.f / (sumh + 1e-16f);

    float4 a0 = make_float4(0.f, 0.f, 0.f, 0.f);
    float4 a1 = make_float4(0.f, 0.f, 0.f, 0.f);
    const int coff = lane * 8;
    for (int e = 0; e < cnt; e++) {
        int s = g_csr[start + e];
        float av = __ldg(&g_as1[s * 4 + hh]);
        float al = expf(lrelu(av + advh) - mh) * invh;
        const float* row = &g_h1[(size_t)s * F1 + coff];
        float4 v0 = *(const float4*)row;
        float4 v1 = *(const float4*)(row + 4);
        a0.x = fmaf(al, v0.x, a0.x); a0.y = fmaf(al, v0.y, a0.y);
        a0.z = fmaf(al, v0.z, a0.z); a0.w = fmaf(al, v0.w, a0.w);
        a1.x = fmaf(al, v1.x, a1.x); a1.y = fmaf(al, v1.y, a1.y);
        a1.z = fmaf(al, v1.z, a1.z); a1.w = fmaf(al, v1.w, a1.w);
    }

    float4 bb0 = *(const float4*)&b1[coff];
    float4 bb1 = *(const float4*)&b1[coff + 4];
    float r0 = a0.x + bb0.x, r1 = a0.y + bb0.y, r2 = a0.z + bb0.z, r3 = a0.w + bb0.w;
    float r4 = a1.x + bb1.x, r5 = a1.y + bb1.y, r6 = a1.z + bb1.z, r7 = a1.w + bb1.w;
    r0 = r0 > 0.f ? r0 : expm1f(r0); r1 = r1 > 0.f ? r1 : expm1f(r1);
    r2 = r2 > 0.f ? r2 : expm1f(r2); r3 = r3 > 0.f ? r3 : expm1f(r3);
    r4 = r4 > 0.f ? r4 : expm1f(r4); r5 = r5 > 0.f ? r5 : expm1f(r5);
    r6 = r6 > 0.f ? r6 : expm1f(r6); r7 = r7 > 0.f ? r7 : expm1f(r7);
    float* orow = &g_hmid[(size_t)node * F1 + coff];
    *(float4*)orow       = make_float4(r0, r1, r2, r3);
    *(float4*)(orow + 4) = make_float4(r4, r5, r6, r7);
}

// ---------------- GEMM2 + fused attention dots ----------------
#define BM2 128
#define BK2 32
#define A2PAD 132
__global__ __launch_bounds__(256) void k_gemm2(const float* __restrict__ W2,
                                               const float* __restrict__ atts,
                                               const float* __restrict__ attd) {
    __shared__ __align__(16) float As2t[BK2][A2PAD];
    __shared__ __align__(16) float Ws[BK2][F2];
    const int bm = blockIdx.x * BM2;
    const int t = threadIdx.x;
    const int tx = t & 7;
    const int ty = t >> 3;
    float acc[4][5];
#pragma unroll
    for (int i = 0; i < 4; i++)
#pragma unroll
        for (int j = 0; j < 5; j++) acc[i][j] = 0.f;

    for (int k0 = 0; k0 < F1; k0 += BK2) {
#pragma unroll
        for (int r = 0; r < 4; r++) {
            int f = t + r * 256;
            int row = f >> 3;
            int cv = (f & 7) * 4;
            float4 v = make_float4(0.f, 0.f, 0.f, 0.f);
            int gr = bm + row;
            if (gr < N_NODES) v = *(const float4*)&g_hmid[(size_t)gr * F1 + k0 + cv];
            As2t[cv + 0][row] = v.x;
            As2t[cv + 1][row] = v.y;
            As2t[cv + 2][row] = v.z;
            As2t[cv + 3][row] = v.w;
        }
        for (int idx = t; idx < BK2 * F2; idx += 256) {
            int r = idx / F2, c = idx % F2;
            Ws[r][c] = W2[(size_t)(k0 + r) * F2 + c];
        }
        __syncthreads();
#pragma unroll
        for (int kk = 0; kk < BK2; kk++) {
            float4 a4 = *(const float4*)&As2t[kk][ty * 4];
            float a[4] = {a4.x, a4.y, a4.z, a4.w};
            float b[5];
#pragma unroll
            for (int j = 0; j < 5; j++) b[j] = Ws[kk][tx * 5 + j];
#pragma unroll
            for (int i = 0; i < 4; i++)
#pragma unroll
                for (int j = 0; j < 5; j++) acc[i][j] = fmaf(a[i], b[j], acc[i][j]);
        }
        __syncthreads();
    }

    float avS[5], avD[5];
#pragma unroll
    for (int j = 0; j < 5; j++) { avS[j] = atts[tx * 5 + j]; avD[j] = attd[tx * 5 + j]; }
#pragma unroll
    for (int i = 0; i < 4; i++) {
        int gr = bm + ty * 4 + i;
        if (gr < N_NODES)
#pragma unroll
            for (int j = 0; j < 5; j++)
                g_h2[(size_t)gr * F2 + tx * 5 + j] = acc[i][j];
        float ps = 0.f, pd = 0.f;
#pragma unroll
        for (int j = 0; j < 5; j++) {
            ps = fmaf(acc[i][j], avS[j], ps);
            pd = fmaf(acc[i][j], avD[j], pd);
        }
#pragma unroll
        for (int off = 4; off; off >>= 1) {
            ps += __shfl_down_sync(0xffffffffu, ps, off, 8);
            pd += __shfl_down_sync(0xffffffffu, pd, off, 8);
        }
        if (tx == 0 && gr < N_NODES) { g_as2[gr] = ps; g_ad2[gr] = pd; }
    }
}

// ---------------- layer-2 aggregation + log_softmax: WARP per node ----------------
__global__ __launch_bounds__(256) void k_agg2w(const float* __restrict__ b2,
                                               float* __restrict__ out) {
    const int node = blockIdx.x * 8 + (threadIdx.x >> 5);
    const int lane = threadIdx.x & 31;
    const int start = g_rowstart[node];
    const int cnt = g_rowstart[node + 1] - start;
    const float adv = g_ad2[node];

    float m = NINF;
    for (int e = lane; e < cnt; e += 32)
        m = fmaxf(m, lrelu(g_as2[g_csr[start + e]] + adv));
#pragma unroll
    for (int off = 16; off; off >>= 1)
        m = fmaxf(m, __shfl_xor_sync(0xffffffffu, m, off));

    float se = 0.f;
    for (int e = lane; e < cnt; e += 32)
        se += expf(lrelu(g_as2[g_csr[start + e]] + adv) - m);
#pragma unroll
    for (int off = 16; off; off >>= 1)
        se += __shfl_xor_sync(0xffffffffu, se, off);
    const float inv = 1.f / (se + 1e-16f);

    float a0 = 0.f, a1 = 0.f;
    for (int e = 0; e < cnt; e++) {
        int s = g_csr[start + e];
        float al = expf(lrelu(__ldg(&g_as2[s]) + adv) - m) * inv;
        const float* row = &g_h2[(size_t)s * F2];
        a0 = fmaf(al, row[lane], a0);
        if (lane < 8) a1 = fmaf(al, row[32 + lane], a1);
    }
    float v0 = a0 + b2[lane];
    float v1 = (lane < 8) ? (a1 + b2[32 + lane]) : NINF;

    float mm = fmaxf(v0, v1);
#pragma unroll
    for (int off = 16; off; off >>= 1)
        mm = fmaxf(mm, __shfl_xor_sync(0xffffffffu, mm, off));
    float s2 = expf(v0 - mm) + ((lane < 8) ? expf(v1 - mm) : 0.f);
#pragma unroll
    for (int off = 16; off; off >>= 1)
        s2 += __shfl_xor_sync(0xffffffffu, s2, off);
    const float lg = logf(s2);

    float* orow = &out[(size_t)node * F2];
    orow[lane] = v0 - mm - lg;
    if (lane < 8) orow[32 + lane] = v1 - mm - lg;
}

// ---------------- launch ----------------
extern "C" void kernel_launch(void* const* d_in, const int* in_sizes, int n_in,
                              void* d_out, int out_size) {
    const float* x   = (const float*)d_in[0];
    const void*  ei  = d_in[1];
    const float* W1  = (const float*)d_in[2];
    const float* as1 = (const float*)d_in[3];
    const float* ad1 = (const float*)d_in[4];
    const float* b1  = (const float*)d_in[5];
    const float* W2  = (const float*)d_in[6];
    const float* as2 = (const float*)d_in[7];
    const float* ad2 = (const float*)d_in[8];
    const float* b2  = (const float*)d_in[9];
    float* out = (float*)d_out;

    static int smem_set = 0;
    if (!smem_set) {
        cudaFuncSetAttribute(k_gemm1h, cudaFuncAttributeMaxDynamicSharedMemorySize, T1_TOTAL);
        smem_set = 1;
    }

    k_init<<<SCAN_BLOCKS, 256>>>((const int*)ei);                // #1
    k_split_w<<<128, 256>>>(W1);                                 // #2
    k_convert_count<<<(E_EDGES + 255) / 256, 256>>>(ei);         // #3
    dim3 gt(2, (N_NODES + 127) / 128);
    k_gemm1h<<<gt, 256, T1_TOTAL>>>(x, as1, ad1);                // #4  <- profiled
    k_bsum<<<SCAN_BLOCKS, 256>>>();                              // #5
    k_rowstart2<<<SCAN_BLOCKS, 256>>>();                         // #6
    k_scatter<<<(E_TOT + 255) / 256, 256>>>();                   // #7
    k_agg1w<<<N_NODES / 8, 256>>>(b1);                           // #8
    k_gemm2<<<(N_NODES + BM2 - 1) / BM2, 256>>>(W2, as2, ad2);   // #9
    k_agg2w<<<N_NODES / 8, 256>>>(b2, out);                      // #10
}

// round 17
// speedup vs baseline: 1.9691x; 1.0328x over previous
#include <cuda_runtime.h>
#include <cuda_bf16.h>
#include <math.h>
#include <stdint.h>

#define N_NODES 50000
#define E_EDGES 800000
#define E_TOT   (E_EDGES + N_NODES)
#define IN_DIM  512
#define F1      256
#define NH1     4
#define F2      40
#define NEG_SLOPE 0.2f
#define NINF (-__int_as_float(0x7f800000))
#define SCAN_BLOCKS 196

// ---------------- scratch ----------------
__device__ int   g_is64;
__device__ int   g_src[E_EDGES];
__device__ int   g_dst[E_EDGES];
__device__ int   g_deg[N_NODES];
__device__ int   g_bsum[SCAN_BLOCKS];
__device__ int   g_rowstart[N_NODES + 1];
__device__ int   g_cursor[N_NODES];
__device__ int   g_csr[E_TOT];
__device__ __align__(16) uint32_t g_h1b[(size_t)N_NODES * (F1 / 2)];  // packed bf16x2
__device__ __align__(16) float g_as1[N_NODES * NH1];
__device__ __align__(16) float g_ad1[N_NODES * NH1];
__device__ __align__(16) float g_hmid[(size_t)N_NODES * F1];
__device__ __align__(16) float g_h2[(size_t)N_NODES * F2];
__device__ float g_as2[N_NODES];
__device__ float g_ad2[N_NODES];
// bf16 split W1, transposed to [n][k]
__device__ __align__(16) __nv_bfloat16 g_wt1[(size_t)F1 * IN_DIM];
__device__ __align__(16) __nv_bfloat16 g_wt2[(size_t)F1 * IN_DIM];

// ---------------- helpers ----------------
__device__ __forceinline__ float lrelu(float x) { return x > 0.f ? x : NEG_SLOPE * x; }

__device__ __forceinline__ uint32_t smem_u32(const void* p) {
    uint32_t a;
    asm("{ .reg .u64 t; cvta.to.shared.u64 t, %1; cvt.u32.u64 %0, t; }" : "=r"(a) : "l"(p));
    return a;
}

#define LDSM_X4(r, a) \
    asm volatile("ldmatrix.sync.aligned.m8n8.x4.shared.b16 {%0,%1,%2,%3}, [%4];" \
        : "=r"((r)[0]), "=r"((r)[1]), "=r"((r)[2]), "=r"((r)[3]) : "r"(a))

#define MMA_BF16(c, a, b0, b1) \
    asm volatile("mma.sync.aligned.m16n8k16.row.col.f32.bf16.bf16.f32 " \
        "{%0,%1,%2,%3}, {%4,%5,%6,%7}, {%8,%9}, {%0,%1,%2,%3};" \
        : "+f"((c)[0]), "+f"((c)[1]), "+f"((c)[2]), "+f"((c)[3]) \
        : "r"((a)[0]), "r"((a)[1]), "r"((a)[2]), "r"((a)[3]), "r"(b0), "r"(b1))

#define CP_ASYNC16(dst, src) \
    asm volatile("cp.async.cg.shared.global [%0], [%1], 16;" :: "r"(dst), "l"(src) : "memory")
#define CP_COMMIT() asm volatile("cp.async.commit_group;" ::: "memory")
#define CP_WAIT0()  asm volatile("cp.async.wait_group 0;" ::: "memory")

// ---------------- init ----------------
__global__ void k_init(const int* e32) {
    int i = blockIdx.x * blockDim.x + threadIdx.x;
    if (i < N_NODES) g_deg[i] = 1;
    if (i == 0) {
        int allzero = 1;
        for (int j = 1; j < 256; j += 2) if (e32[j] != 0) allzero = 0;
        g_is64 = allzero;
    }
}

__global__ void k_convert_count(const void* eptr) {
    int i = blockIdx.x * blockDim.x + threadIdx.x;
    if (i >= E_EDGES) return;
    int s, d;
    if (g_is64) {
        const long long* e = (const long long*)eptr;
        s = (int)e[i];
        d = (int)e[E_EDGES + i];
    } else {
        const int* e = (const int*)eptr;
        s = e[i];
        d = e[E_EDGES + i];
    }
    g_src[i] = s;
    g_dst[i] = d;
    atomicAdd(&g_deg[d], 1);
}

// ---------------- W1 transpose + bf16 split (tiled) ----------------
__global__ void k_split_w(const float* __restrict__ W) {
    __shared__ float tile[32][33];
    const int t = threadIdx.x;
    const int tx = t & 31, ty = t >> 5;
    const int k0 = (blockIdx.x & 15) * 32;
    const int n0 = (blockIdx.x >> 4) * 32;
#pragma unroll
    for (int i = 0; i < 4; i++)
        tile[ty * 4 + i][tx] = W[(size_t)(k0 + ty * 4 + i) * F1 + n0 + tx];
    __syncthreads();
#pragma unroll
    for (int i = 0; i < 4; i++) {
        int n = n0 + ty * 4 + i;
        float v = tile[tx][ty * 4 + i];
        __nv_bfloat16 h = __float2bfloat16(v);
        g_wt1[(size_t)n * IN_DIM + k0 + tx] = h;
        g_wt2[(size_t)n * IN_DIM + k0 + tx] = __float2bfloat16(v - __bfloat162float(h));
    }
}

// ---------------- CSR scan ----------------
__global__ void k_bsum() {
    __shared__ int sh[256];
    const int b = blockIdx.x, t = threadIdx.x;
    const int i = b * 256 + t;
    sh[t] = (i < N_NODES) ? g_deg[i] : 0;
    __syncthreads();
#pragma unroll
    for (int off = 128; off; off >>= 1) {
        if (t < off) sh[t] += sh[t + off];
        __syncthreads();
    }
    if (t == 0) g_bsum[b] = sh[0];
}

__global__ void k_rowstart2() {
    __shared__ int sred[256];
    __shared__ int sh[256];
    const int b = blockIdx.x, t = threadIdx.x;
    sred[t] = (t < b) ? g_bsum[t] : 0;
    __syncthreads();
#pragma unroll
    for (int off = 128; off; off >>= 1) {
        if (t < off) sred[t] += sred[t + off];
        __syncthreads();
    }
    const int boff = sred[0];
    const int i = b * 256 + t;
    const int v = (i < N_NODES) ? g_deg[i] : 0;
    sh[t] = v;
    __syncthreads();
#pragma unroll
    for (int off = 1; off < 256; off <<= 1) {
        int u = (t >= off) ? sh[t - off] : 0;
        __syncthreads();
        sh[t] += u;
        __syncthreads();
    }
    const int excl = boff + sh[t] - v;
    if (i < N_NODES) {
        g_rowstart[i] = excl;
        g_cursor[i]   = excl;
        if (i == N_NODES - 1) g_rowstart[N_NODES] = excl + v;
    }
}

__global__ void k_scatter() {
    int i = blockIdx.x * blockDim.x + threadIdx.x;
    if (i >= E_TOT) return;
    int s, d;
    if (i < E_EDGES) { s = g_src[i]; d = g_dst[i]; }
    else             { s = d = i - E_EDGES; }
    int pos = atomicAdd(&g_cursor[d], 1);
    g_csr[pos] = s;
}

// ---------------- GEMM1 via HMMA, double-buffered, K-chunk 16, 2 CTAs/SM ----
#define KCH 16
#define RSTRIDE 48
#define TILE_SZ (128 * RSTRIDE)       // 6144
#define T1_A1 0
#define T1_A2 TILE_SZ
#define T1_B1 (2 * TILE_SZ)
#define T1_B2 (3 * TILE_SZ)
#define BUFSZ (4 * TILE_SZ)           // 24576
#define T1_SA (2 * BUFSZ)             // 49152
#define T1_SD (T1_SA + 512)
#define T1_TOTAL (T1_SD + 512)        // 50176

__global__ __launch_bounds__(256, 2) void k_gemm1h(const float* __restrict__ x,
                                                   const float* __restrict__ atts,
                                                   const float* __restrict__ attd) {
    extern __shared__ __align__(16) char smem[];
    const uint32_t sb = smem_u32(smem);
    const int t = threadIdx.x;
    const int wid = t >> 5, lane = t & 31;
    const int bm = blockIdx.y * 128;
    const int bn = blockIdx.x * 128;
    const int wm = (wid & 3) * 32;
    const int wn = (wid >> 2) * 64;

    if (t < 128) {
        ((float*)(smem + T1_SA))[t] = atts[bn + t];
        ((float*)(smem + T1_SD))[t] = attd[bn + t];
    }

    float acc[2][8][4];
#pragma unroll
    for (int mi = 0; mi < 2; mi++)
#pragma unroll
        for (int ni = 0; ni < 8; ni++)
#pragma unroll
            for (int q = 0; q < 4; q++) acc[mi][ni][q] = 0.f;

    const int lr = lane & 7;
    const int aRow = lr + 8 * ((lane >> 3) & 1);
    const int aKk  = 8 * (lane >> 4);
    const int bRow = lr + 8 * (lane >> 4);
    const int bKk  = 8 * ((lane >> 3) & 1);

    auto issueB = [&](int k0, uint32_t base) {
        {
            int row = t >> 1, half = t & 1;
            const __nv_bfloat16* s1 = g_wt1 + (size_t)(bn + row) * IN_DIM + k0 + half * 8;
            CP_ASYNC16(base + T1_B1 + row * RSTRIDE + half * 16, s1);
            const __nv_bfloat16* s2 = g_wt2 + (size_t)(bn + row) * IN_DIM + k0 + half * 8;
            CP_ASYNC16(base + T1_B2 + row * RSTRIDE + half * 16, s2);
        }
        CP_COMMIT();
    };
    auto loadA = [&](int k0, float4* pa) {
#pragma unroll
        for (int q = 0; q < 2; q++) {
            int f = t + q * 256;
            int row = f >> 2, jc = (f & 3) * 4;
            pa[q] = make_float4(0.f, 0.f, 0.f, 0.f);
            int gr = bm + row;
            if (gr < N_NODES) pa[q] = *(const float4*)&x[(size_t)gr * IN_DIM + k0 + jc];
        }
    };
    auto storeA = [&](const float4* pa, uint32_t baseOff) {
        char* bp = smem + baseOff;
#pragma unroll
        for (int q = 0; q < 2; q++) {
            int f = t + q * 256;
            int row = f >> 2, jc = (f & 3) * 4;
            float4 v = pa[q];
            __nv_bfloat16 h0 = __float2bfloat16(v.x), h1 = __float2bfloat16(v.y);
            __nv_bfloat16 h2 = __float2bfloat16(v.z), h3 = __float2bfloat16(v.w);
            __nv_bfloat16 l0 = __float2bfloat16(v.x - __bfloat162float(h0));
            __nv_bfloat16 l1 = __float2bfloat16(v.y - __bfloat162float(h1));
            __nv_bfloat16 l2 = __float2bfloat16(v.z - __bfloat162float(h2));
            __nv_bfloat16 l3 = __float2bfloat16(v.w - __bfloat162float(h3));
            uint2 hi, lo;
            hi.x = (uint32_t)__bfloat16_as_ushort(h0) | ((uint32_t)__bfloat16_as_ushort(h1) << 16);
            hi.y = (uint32_t)__bfloat16_as_ushort(h2) | ((uint32_t)__bfloat16_as_ushort(h3) << 16);
            lo.x = (uint32_t)__bfloat16_as_ushort(l0) | ((uint32_t)__bfloat16_as_ushort(l1) << 16);
            lo.y = (uint32_t)__bfloat16_as_ushort(l2) | ((uint32_t)__bfloat16_as_ushort(l3) << 16);
            *(uint2*)(bp + T1_A1 + row * RSTRIDE + jc * 2) = hi;
            *(uint2*)(bp + T1_A2 + row * RSTRIDE + jc * 2) = lo;
        }
    };

    // prologue
    {
        float4 pa0[2];
        loadA(0, pa0);
        issueB(0, sb + 0);
        storeA(pa0, 0);
        CP_WAIT0();
    }
    __syncthreads();

    uint32_t buf = 0;
    float4 pa[2];
    for (int c = 0; c < IN_DIM / KCH; c++) {
        const int k0 = c * KCH;
        const bool has_next = (c + 1) < IN_DIM / KCH;
        const uint32_t nbuf = buf ^ BUFSZ;
        if (has_next) {
            loadA(k0 + KCH, pa);
            issueB(k0 + KCH, sb + nbuf);
        }

        const uint32_t sA1 = sb + buf + T1_A1;
        const uint32_t sA2 = sb + buf + T1_A2;
        const uint32_t sB1 = sb + buf + T1_B1;
        const uint32_t sB2 = sb + buf + T1_B2;
        {
            uint32_t a1f[2][4], a2f[2][4];
#pragma unroll
            for (int mi = 0; mi < 2; mi++) {
                uint32_t off = (uint32_t)((wm + mi * 16 + aRow) * RSTRIDE + aKk * 2);
                LDSM_X4(a1f[mi], sA1 + off);
                LDSM_X4(a2f[mi], sA2 + off);
            }
#pragma unroll
            for (int njp = 0; njp < 4; njp++) {
                uint32_t b1f[4], b2f[4];
                uint32_t off = (uint32_t)((wn + njp * 16 + bRow) * RSTRIDE + bKk * 2);
                LDSM_X4(b1f, sB1 + off);
                LDSM_X4(b2f, sB2 + off);
#pragma unroll
                for (int h = 0; h < 2; h++) {
                    int ni = njp * 2 + h;
#pragma unroll
                    for (int mi = 0; mi < 2; mi++) {
                        MMA_BF16(acc[mi][ni], a1f[mi], b1f[2 * h], b1f[2 * h + 1]);
                        MMA_BF16(acc[mi][ni], a1f[mi], b2f[2 * h], b2f[2 * h + 1]);
                        MMA_BF16(acc[mi][ni], a2f[mi], b1f[2 * h], b1f[2 * h + 1]);
                    }
                }
            }
        }

        if (has_next) {
            storeA(pa, nbuf);
            CP_WAIT0();
        }
        __syncthreads();
        buf = nbuf;
    }

    // epilogue: store h1 (packed bf16x2) + direct attention-dot stores
    const int group = lane >> 2, qt = lane & 3;
    const float* sa = (const float*)(smem + T1_SA);
    const float* sd = (const float*)(smem + T1_SD);
    const int head = (bn >> 6) + (wn >> 6);
#pragma unroll
    for (int mi = 0; mi < 2; mi++) {
#pragma unroll
        for (int hr = 0; hr < 2; hr++) {
            int r = bm + wm + mi * 16 + group + hr * 8;
            float ps = 0.f, pd = 0.f;
            if (r < N_NODES) {
#pragma unroll
                for (int ni = 0; ni < 8; ni++) {
                    float v0 = acc[mi][ni][hr * 2], v1 = acc[mi][ni][hr * 2 + 1];
                    int cl = wn + ni * 8 + qt * 2;
                    __nv_bfloat162 pkv = __floats2bfloat162_rn(v0, v1);
                    g_h1b[(size_t)r * (F1 / 2) + ((bn + cl) >> 1)] = *(uint32_t*)&pkv;
                    ps = fmaf(v0, sa[cl], ps); ps = fmaf(v1, sa[cl + 1], ps);
                    pd = fmaf(v0, sd[cl], pd); pd = fmaf(v1, sd[cl + 1], pd);
                }
            }
            ps += __shfl_xor_sync(0xffffffffu, ps, 1);
            ps += __shfl_xor_sync(0xffffffffu, ps, 2);
            pd += __shfl_xor_sync(0xffffffffu, pd, 1);
            pd += __shfl_xor_sync(0xffffffffu, pd, 2);
            if (qt == 0 && r < N_NODES) {
                g_as1[r * 4 + head] = ps;
                g_ad1[r * 4 + head] = pd;
            }
        }
    }
}

// ---------------- layer-1 aggregation: WARP per node, bf16 gather ----------------
__global__ __launch_bounds__(256) void k_agg1w(const float* __restrict__ b1) {
    const int node = blockIdx.x * 8 + (threadIdx.x >> 5);
    const int lane = threadIdx.x & 31;
    const int start = g_rowstart[node];
    const int cnt = g_rowstart[node + 1] - start;

    float4 adv = *(const float4*)&g_ad1[node * 4];

    float m0 = NINF, m1 = NINF, m2 = NINF, m3 = NINF;
    for (int e = lane; e < cnt; e += 32) {
        int s = g_csr[start + e];
        float4 av = *(const float4*)&g_as1[s * 4];
        m0 = fmaxf(m0, lrelu(av.x + adv.x));
        m1 = fmaxf(m1, lrelu(av.y + adv.y));
        m2 = fmaxf(m2, lrelu(av.z + adv.z));
        m3 = fmaxf(m3, lrelu(av.w + adv.w));
    }
#pragma unroll
    for (int off = 16; off; off >>= 1) {
        m0 = fmaxf(m0, __shfl_xor_sync(0xffffffffu, m0, off));
        m1 = fmaxf(m1, __shfl_xor_sync(0xffffffffu, m1, off));
        m2 = fmaxf(m2, __shfl_xor_sync(0xffffffffu, m2, off));
        m3 = fmaxf(m3, __shfl_xor_sync(0xffffffffu, m3, off));
    }

    float s0 = 0.f, s1 = 0.f, s2 = 0.f, s3 = 0.f;
    for (int e = lane; e < cnt; e += 32) {
        int s = g_csr[start + e];
        float4 av = *(const float4*)&g_as1[s * 4];
        s0 += expf(lrelu(av.x + adv.x) - m0);
        s1 += expf(lrelu(av.y + adv.y) - m1);
        s2 += expf(lrelu(av.z + adv.z) - m2);
        s3 += expf(lrelu(av.w + adv.w) - m3);
    }
#pragma unroll
    for (int off = 16; off; off >>= 1) {
        s0 += __shfl_xor_sync(0xffffffffu, s0, off);
        s1 += __shfl_xor_sync(0xffffffffu, s1, off);
        s2 += __shfl_xor_sync(0xffffffffu, s2, off);
        s3 += __shfl_xor_sync(0xffffffffu, s3, off);
    }

    const int hh = lane >> 3;
    float advh = (hh == 0) ? adv.x : (hh == 1) ? adv.y : (hh == 2) ? adv.z : adv.w;
    float mh   = (hh == 0) ? m0    : (hh == 1) ? m1    : (hh == 2) ? m2    : m3;
    float sumh = (hh == 0) ? s0    : (hh == 1) ? s1    : (hh == 2) ? s2    : s3;
    const float invh = 1.f / (sumh + 1e-16f);

    float a0 = 0.f, a1 = 0.f, a2 = 0.f, a3 = 0.f;
    float a4 = 0.f, a5 = 0.f, a6 = 0.f, a7 = 0.f;
    const int coff = lane * 8;
    for (int e = 0; e < cnt; e++) {
        int s = g_csr[start + e];
        float av = __ldg(&g_as1[s * 4 + hh]);
        float al = expf(lrelu(av + advh) - mh) * invh;
        uint4 v = *(const uint4*)&g_h1b[(size_t)s * (F1 / 2) + lane * 4];
        float2 f0 = __bfloat1622float2(*(__nv_bfloat162*)&v.x);
        float2 f1 = __bfloat1622float2(*(__nv_bfloat162*)&v.y);
        float2 f2 = __bfloat1622float2(*(__nv_bfloat162*)&v.z);
        float2 f3 = __bfloat1622float2(*(__nv_bfloat162*)&v.w);
        a0 = fmaf(al, f0.x, a0); a1 = fmaf(al, f0.y, a1);
        a2 = fmaf(al, f1.x, a2); a3 = fmaf(al, f1.y, a3);
        a4 = fmaf(al, f2.x, a4); a5 = fmaf(al, f2.y, a5);
        a6 = fmaf(al, f3.x, a6); a7 = fmaf(al, f3.y, a7);
    }

    float4 bb0 = *(const float4*)&b1[coff];
    float4 bb1 = *(const float4*)&b1[coff + 4];
    float r0 = a0 + bb0.x, r1 = a1 + bb0.y, r2 = a2 + bb0.z, r3 = a3 + bb0.w;
    float r4 = a4 + bb1.x, r5 = a5 + bb1.y, r6 = a6 + bb1.z, r7 = a7 + bb1.w;
    r0 = r0 > 0.f ? r0 : expm1f(r0); r1 = r1 > 0.f ? r1 : expm1f(r1);
    r2 = r2 > 0.f ? r2 : expm1f(r2); r3 = r3 > 0.f ? r3 : expm1f(r3);
    r4 = r4 > 0.f ? r4 : expm1f(r4); r5 = r5 > 0.f ? r5 : expm1f(r5);
    r6 = r6 > 0.f ? r6 : expm1f(r6); r7 = r7 > 0.f ? r7 : expm1f(r7);
    float* orow = &g_hmid[(size_t)node * F1 + coff];
    *(float4*)orow       = make_float4(r0, r1, r2, r3);
    *(float4*)(orow + 4) = make_float4(r4, r5, r6, r7);
}

// ---------------- GEMM2 + fused attention dots ----------------
#define BM2 128
#define BK2 32
#define A2PAD 132
__global__ __launch_bounds__(256) void k_gemm2(const float* __restrict__ W2,
                                               const float* __restrict__ atts,
                                               const float* __restrict__ attd) {
    __shared__ __align__(16) float As2t[BK2][A2PAD];
    __shared__ __align__(16) float Ws[BK2][F2];
    const int bm = blockIdx.x * BM2;
    const int t = threadIdx.x;
    const int tx = t & 7;
    const int ty = t >> 3;
    float acc[4][5];
#pragma unroll
    for (int i = 0; i < 4; i++)
#pragma unroll
        for (int j = 0; j < 5; j++) acc[i][j] = 0.f;

    for (int k0 = 0; k0 < F1; k0 += BK2) {
#pragma unroll
        for (int r = 0; r < 4; r++) {
            int f = t + r * 256;
            int row = f >> 3;
            int cv = (f & 7) * 4;
            float4 v = make_float4(0.f, 0.f, 0.f, 0.f);
            int gr = bm + row;
            if (gr < N_NODES) v = *(const float4*)&g_hmid[(size_t)gr * F1 + k0 + cv];
            As2t[cv + 0][row] = v.x;
            As2t[cv + 1][row] = v.y;
            As2t[cv + 2][row] = v.z;
            As2t[cv + 3][row] = v.w;
        }
        for (int idx = t; idx < BK2 * F2; idx += 256) {
            int r = idx / F2, c = idx % F2;
            Ws[r][c] = W2[(size_t)(k0 + r) * F2 + c];
        }
        __syncthreads();
#pragma unroll
        for (int kk = 0; kk < BK2; kk++) {
            float4 a4 = *(const float4*)&As2t[kk][ty * 4];
            float a[4] = {a4.x, a4.y, a4.z, a4.w};
            float b[5];
#pragma unroll
            for (int j = 0; j < 5; j++) b[j] = Ws[kk][tx * 5 + j];
#pragma unroll
            for (int i = 0; i < 4; i++)
#pragma unroll
                for (int j = 0; j < 5; j++) acc[i][j] = fmaf(a[i], b[j], acc[i][j]);
        }
        __syncthreads();
    }

    float avS[5], avD[5];
#pragma unroll
    for (int j = 0; j < 5; j++) { avS[j] = atts[tx * 5 + j]; avD[j] = attd[tx * 5 + j]; }
#pragma unroll
    for (int i = 0; i < 4; i++) {
        int gr = bm + ty * 4 + i;
        if (gr < N_NODES)
#pragma unroll
            for (int j = 0; j < 5; j++)
                g_h2[(size_t)gr * F2 + tx * 5 + j] = acc[i][j];
        float ps = 0.f, pd = 0.f;
#pragma unroll
        for (int j = 0; j < 5; j++) {
            ps = fmaf(acc[i][j], avS[j], ps);
            pd = fmaf(acc[i][j], avD[j], pd);
        }
#pragma unroll
        for (int off = 4; off; off >>= 1) {
            ps += __shfl_down_sync(0xffffffffu, ps, off, 8);
            pd += __shfl_down_sync(0xffffffffu, pd, off, 8);
        }
        if (tx == 0 && gr < N_NODES) { g_as2[gr] = ps; g_ad2[gr] = pd; }
    }
}

// ---------------- layer-2 aggregation + log_softmax: WARP per node ----------------
__global__ __launch_bounds__(256) void k_agg2w(const float* __restrict__ b2,
                                               float* __restrict__ out) {
    const int node = blockIdx.x * 8 + (threadIdx.x >> 5);
    const int lane = threadIdx.x & 31;
    const int start = g_rowstart[node];
    const int cnt = g_rowstart[node + 1] - start;
    const float adv = g_ad2[node];

    float m = NINF;
    for (int e = lane; e < cnt; e += 32)
        m = fmaxf(m, lrelu(g_as2[g_csr[start + e]] + adv));
#pragma unroll
    for (int off = 16; off; off >>= 1)
        m = fmaxf(m, __shfl_xor_sync(0xffffffffu, m, off));

    float se = 0.f;
    for (int e = lane; e < cnt; e += 32)
        se += expf(lrelu(g_as2[g_csr[start + e]] + adv) - m);
#pragma unroll
    for (int off = 16; off; off >>= 1)
        se += __shfl_xor_sync(0xffffffffu, se, off);
    const float inv = 1.f / (se + 1e-16f);

    float a0 = 0.f, a1 = 0.f;
    for (int e = 0; e < cnt; e++) {
        int s = g_csr[start + e];
        float al = expf(lrelu(__ldg(&g_as2[s]) + adv) - m) * inv;
        const float* row = &g_h2[(size_t)s * F2];
        a0 = fmaf(al, row[lane], a0);
        if (lane < 8) a1 = fmaf(al, row[32 + lane], a1);
    }
    float v0 = a0 + b2[lane];
    float v1 = (lane < 8) ? (a1 + b2[32 + lane]) : NINF;

    float mm = fmaxf(v0, v1);
#pragma unroll
    for (int off = 16; off; off >>= 1)
        mm = fmaxf(mm, __shfl_xor_sync(0xffffffffu, mm, off));
    float s2 = expf(v0 - mm) + ((lane < 8) ? expf(v1 - mm) : 0.f);
#pragma unroll
    for (int off = 16; off; off >>= 1)
        s2 += __shfl_xor_sync(0xffffffffu, s2, off);
    const float lg = logf(s2);

    float* orow = &out[(size_t)node * F2];
    orow[lane] = v0 - mm - lg;
    if (lane < 8) orow[32 + lane] = v1 - mm - lg;
}

// ---------------- launch ----------------
extern "C" void kernel_launch(void* const* d_in, const int* in_sizes, int n_in,
                              void* d_out, int out_size) {
    const float* x   = (const float*)d_in[0];
    const void*  ei  = d_in[1];
    const float* W1  = (const float*)d_in[2];
    const float* as1 = (const float*)d_in[3];
    const float* ad1 = (const float*)d_in[4];
    const float* b1  = (const float*)d_in[5];
    const float* W2  = (const float*)d_in[6];
    const float* as2 = (const float*)d_in[7];
    const float* ad2 = (const float*)d_in[8];
    const float* b2  = (const float*)d_in[9];
    float* out = (float*)d_out;

    static int smem_set = 0;
    if (!smem_set) {
        cudaFuncSetAttribute(k_gemm1h, cudaFuncAttributeMaxDynamicSharedMemorySize, T1_TOTAL);
        smem_set = 1;
    }

    k_init<<<SCAN_BLOCKS, 256>>>((const int*)ei);                // #1
    k_split_w<<<128, 256>>>(W1);                                 // #2
    k_convert_count<<<(E_EDGES + 255) / 256, 256>>>(ei);         // #3
    dim3 gt(2, (N_NODES + 127) / 128);
    k_gemm1h<<<gt, 256, T1_TOTAL>>>(x, as1, ad1);                // #4  <- profiled
    k_bsum<<<SCAN_BLOCKS, 256>>>();                              // #5
    k_rowstart2<<<SCAN_BLOCKS, 256>>>();                         // #6
    k_scatter<<<(E_TOT + 255) / 256, 256>>>();                   // #7
    k_agg1w<<<N_NODES / 8, 256>>>(b1);                           // #8
    k_gemm2<<<(N_NODES + BM2 - 1) / BM2, 256>>>(W2, as2, ad2);   // #9
    k_agg2w<<<N_NODES / 8, 256>>>(b2, out);                      // #10
}